// round 1
// baseline (speedup 1.0000x reference)
#include <cuda_runtime.h>
#include <math.h>

// ---------------------------------------------------------------------------
// Problem constants
//   base_feat: (32,256,512,4,4) f32  -> 8192 samples of (512,16)
//   rois:      (8192,4) i32
//   w1:(512,256) b1:(256) w2:(256,128) b2:(128) wl:(2048,1024) bl:(1024)
//   out: (32,256,1024) f32
//
// Algebra: feat[o,i,j] = b2[o]
//                      + S1[o]                 if i,j both odd
//                      + Z[o][i==7][j==7]      if additionally i,j in {3,7}
// with S1 = b1·w2 and Z[o,a,b] = sum_k x[k,1+a,1+b] * (w1@w2)[k,o]
// ---------------------------------------------------------------------------

#define NSAMP 8192
#define SPB   8   // samples per pool block

__device__ float g_W[512 * 128];                 // w1 @ w2
__device__ float g_S1[128];                      // b1 @ w2
__device__ float g_P[(size_t)NSAMP * 2048];      // pooled rows (GEMM A matrix)

// ---------------------------------------------------------------------------
// Kernel 1: W = w1 @ w2 (512x128), S1 = b1 @ w2 (128)
// grid 513 blocks x 128 threads; block 512 computes S1.
// ---------------------------------------------------------------------------
__global__ void prep_kernel(const float* __restrict__ w1,
                            const float* __restrict__ b1,
                            const float* __restrict__ w2) {
    const int o = threadIdx.x;   // 0..127
    const int k = blockIdx.x;    // 0..512
    float acc = 0.f;
    if (k < 512) {
        #pragma unroll 4
        for (int c = 0; c < 256; ++c)
            acc = fmaf(w1[k * 256 + c], w2[c * 128 + o], acc);
        g_W[k * 128 + o] = acc;
    } else {
        #pragma unroll 4
        for (int c = 0; c < 256; ++c)
            acc = fmaf(b1[c], w2[c * 128 + o], acc);
        g_S1[o] = acc;
    }
}

// ---------------------------------------------------------------------------
// Kernel 2: per-sample Z (512x4 dot products) + categorized max-pool.
// One block handles SPB samples; thread o = output channel.
// Writes pooled rows (2048 f32 per sample, o-major then 4x4 cell) into g_P.
// ---------------------------------------------------------------------------
__global__ __launch_bounds__(128) void pool_kernel(const float* __restrict__ base,
                                                   const int* __restrict__ rois,
                                                   const float* __restrict__ b2) {
    __shared__ float4 xs[SPB][512];   // (f[1,1], f[1,2], f[2,1], f[2,2]) per k
    const int n0 = blockIdx.x * SPB;
    const int o  = threadIdx.x;

    // Cooperative load of the center 2x2 of each 4x4 spatial tile.
    // floats (k*16 + 5,6) live in float4 q=1; (k*16 + 9,10) in q=2.
    for (int s = 0; s < SPB; ++s) {
        const float4* x4 = (const float4*)(base + (size_t)(n0 + s) * 8192);
        float2* dst = (float2*)xs[s];
        for (int j = o; j < 1024; j += 128) {
            const int k = j >> 1;
            const int q = 1 + (j & 1);
            float4 v = x4[k * 4 + q];
            dst[j] = make_float2(v.y, v.z);  // (f5,f6) or (f9,f10)
        }
    }
    __syncthreads();

    // Z accumulation: acc[s] = {Z00,Z01,Z10,Z11}
    float4 acc[SPB];
    #pragma unroll
    for (int s = 0; s < SPB; ++s) acc[s] = make_float4(0.f, 0.f, 0.f, 0.f);

    for (int k = 0; k < 512; ++k) {
        const float w = g_W[k * 128 + o];
        #pragma unroll
        for (int s = 0; s < SPB; ++s) {
            float4 xv = xs[s][k];
            acc[s].x = fmaf(xv.x, w, acc[s].x);
            acc[s].y = fmaf(xv.y, w, acc[s].y);
            acc[s].z = fmaf(xv.z, w, acc[s].z);
            acc[s].w = fmaf(xv.w, w, acc[s].w);
        }
    }

    const float b2o = b2[o];
    const float s1o = g_S1[o];

    for (int s = 0; s < SPB; ++s) {
        const int n = n0 + s;
        int4 rr = ((const int4*)rois)[n];
        int y0 = rr.x, x0 = rr.y;
        const int h = rr.z - rr.x, w = rr.w - rr.y;
        const bool inb = (rr.x >= 0 && rr.x < 11 && rr.y >= 0 && rr.y < 11 &&
                          rr.z >= 0 && rr.z < 11 && rr.w >= 0 && rr.w < 11);
        int cat;
        if      (inb && h == 4 && w == 4) cat = 0;
        else if (inb && h == 8 && w == 8) cat = 1;
        else if (inb && h == 4 && w == 8) cat = 2;
        else if (inb && h == 6 && w == 8) cat = 3;
        else { cat = 4; y0 = 1; x0 = 1; }

        const float z00 = acc[s].x, z01 = acc[s].y, z10 = acc[s].z, z11 = acc[s].w;
        auto feval = [&](int i, int j) -> float {
            float v = b2o;
            if ((i & 1) && (j & 1)) {
                v += s1o;
                const bool ia = (i == 3) || (i == 7);
                const bool ja = (j == 3) || (j == 7);
                if (ia && ja)
                    v += (i == 3) ? ((j == 3) ? z00 : z01)
                                  : ((j == 3) ? z10 : z11);
            }
            return v;
        };

        float cell[16];
        if (cat == 0) {
            for (int u = 0; u < 4; ++u)
                for (int v = 0; v < 4; ++v)
                    cell[u * 4 + v] = feval(y0 + u, x0 + v);
        } else if (cat == 1) {
            for (int u = 0; u < 4; ++u)
                for (int v = 0; v < 4; ++v) {
                    const int i0 = y0 + 2 * u, j0 = x0 + 2 * v;
                    cell[u * 4 + v] =
                        fmaxf(fmaxf(feval(i0, j0),     feval(i0, j0 + 1)),
                              fmaxf(feval(i0 + 1, j0), feval(i0 + 1, j0 + 1)));
                }
        } else if (cat == 2) {
            for (int u = 0; u < 4; ++u)
                for (int v = 0; v < 4; ++v) {
                    const int j0 = x0 + 2 * v;
                    cell[u * 4 + v] = fmaxf(feval(y0 + u, j0), feval(y0 + u, j0 + 1));
                }
        } else if (cat == 3) {
            // rows padded with -inf at top/bottom: window rows {2u-1, 2u} ∩ [0,6)
            for (int u = 0; u < 4; ++u)
                for (int v = 0; v < 4; ++v) {
                    const int j0 = x0 + 2 * v;
                    float m = -3.402823466e38f;
                    const int r0 = 2 * u - 1, r1 = 2 * u;
                    if (r0 >= 0) m = fmaxf(feval(y0 + r0, j0), feval(y0 + r0, j0 + 1));
                    if (r1 < 6)  m = fmaxf(m, fmaxf(feval(y0 + r1, j0),
                                                    feval(y0 + r1, j0 + 1)));
                    cell[u * 4 + v] = m;
                }
        } else {
            // 3x3 window, stride 2, on the 9x9 slice starting at (1,1)
            for (int u = 0; u < 4; ++u)
                for (int v = 0; v < 4; ++v) {
                    float m = -3.402823466e38f;
                    for (int di = 0; di < 3; ++di)
                        for (int dj = 0; dj < 3; ++dj)
                            m = fmaxf(m, feval(1 + 2 * u + di, 1 + 2 * v + dj));
                    cell[u * 4 + v] = m;
                }
        }

        float4* p4 = (float4*)&g_P[(size_t)n * 2048 + o * 16];
        p4[0] = make_float4(cell[0],  cell[1],  cell[2],  cell[3]);
        p4[1] = make_float4(cell[4],  cell[5],  cell[6],  cell[7]);
        p4[2] = make_float4(cell[8],  cell[9],  cell[10], cell[11]);
        p4[3] = make_float4(cell[12], cell[13], cell[14], cell[15]);
    }
}

// ---------------------------------------------------------------------------
// Kernel 3: out = leaky_relu(P(8192x2048) @ wl(2048x1024) + bl)
// fp32 SIMT GEMM: 128x128 block tile, BK=16, 256 threads, 8x8 per thread.
// ---------------------------------------------------------------------------
__global__ __launch_bounds__(256) void gemm_kernel(const float* __restrict__ Bw,
                                                   const float* __restrict__ bias,
                                                   float* __restrict__ out) {
    __shared__ float As[16][128];   // [k][m]
    __shared__ float Bs[16][128];   // [k][n]
    const int tid = threadIdx.x;
    const int bn = blockIdx.x * 128;
    const int bm = blockIdx.y * 128;
    const int tx = tid & 15, ty = tid >> 4;

    float acc[8][8];
    #pragma unroll
    for (int i = 0; i < 8; ++i)
        #pragma unroll
        for (int j = 0; j < 8; ++j) acc[i][j] = 0.f;

    const int a_row = tid >> 1;          // 0..127
    const int a_c4  = (tid & 1) * 2;     // {0,2}: this thread loads float4 cols a_c4, a_c4+1

    for (int k0 = 0; k0 < 2048; k0 += 16) {
        #pragma unroll
        for (int r = 0; r < 2; ++r) {
            float4 v = *(const float4*)&g_P[(size_t)(bm + a_row) * 2048 + k0 + (a_c4 + r) * 4];
            const int kk = (a_c4 + r) * 4;
            As[kk + 0][a_row] = v.x;
            As[kk + 1][a_row] = v.y;
            As[kk + 2][a_row] = v.z;
            As[kk + 3][a_row] = v.w;
        }
        #pragma unroll
        for (int r = 0; r < 2; ++r) {
            const int idx = tid * 2 + r;         // 0..511
            const int row = idx >> 5, c4 = idx & 31;
            float4 v = *(const float4*)&Bw[(size_t)(k0 + row) * 1024 + bn + c4 * 4];
            *(float4*)&Bs[row][c4 * 4] = v;
        }
        __syncthreads();

        #pragma unroll
        for (int kk = 0; kk < 16; ++kk) {
            float ra[8], rb[8];
            #pragma unroll
            for (int i = 0; i < 8; ++i) ra[i] = As[kk][ty * 8 + i];
            #pragma unroll
            for (int j = 0; j < 8; ++j) rb[j] = Bs[kk][tx * 8 + j];
            #pragma unroll
            for (int i = 0; i < 8; ++i)
                #pragma unroll
                for (int j = 0; j < 8; ++j)
                    acc[i][j] = fmaf(ra[i], rb[j], acc[i][j]);
        }
        __syncthreads();
    }

    #pragma unroll
    for (int i = 0; i < 8; ++i) {
        const int m = bm + ty * 8 + i;
        #pragma unroll
        for (int j = 0; j < 8; j += 4) {
            const int n = bn + tx * 8 + j;
            const float h0 = acc[i][j + 0] + bias[n + 0];
            const float h1 = acc[i][j + 1] + bias[n + 1];
            const float h2 = acc[i][j + 2] + bias[n + 2];
            const float h3 = acc[i][j + 3] + bias[n + 3];
            float4 r;
            r.x = h0 > 0.f ? h0 : 0.01f * h0;
            r.y = h1 > 0.f ? h1 : 0.01f * h1;
            r.z = h2 > 0.f ? h2 : 0.01f * h2;
            r.w = h3 > 0.f ? h3 : 0.01f * h3;
            *(float4*)&out[(size_t)m * 1024 + n] = r;
        }
    }
}

// ---------------------------------------------------------------------------
extern "C" void kernel_launch(void* const* d_in, const int* in_sizes, int n_in,
                              void* d_out, int out_size) {
    const float* base = (const float*)d_in[0];
    const int*   rois = (const int*)d_in[1];
    const float* w1   = (const float*)d_in[2];
    const float* b1   = (const float*)d_in[3];
    const float* w2   = (const float*)d_in[4];
    const float* b2   = (const float*)d_in[5];
    const float* wl   = (const float*)d_in[6];
    const float* bl   = (const float*)d_in[7];
    float* out = (float*)d_out;

    prep_kernel<<<513, 128>>>(w1, b1, w2);
    pool_kernel<<<NSAMP / SPB, 128>>>(base, rois, b2);
    gemm_kernel<<<dim3(1024 / 128, NSAMP / 128), 256>>>(wl, bl, out);
}

// round 3
// speedup vs baseline: 1.8415x; 1.8415x over previous
#include <cuda_runtime.h>
#include <cuda_bf16.h>
#include <math.h>
#include <stdint.h>

// ---------------------------------------------------------------------------
//   base_feat: (32,256,512,4,4) f32 -> 8192 samples of (512,16)
//   rois:(8192,4) i32  w1:(512,256) b1:(256) w2:(256,128) b2:(128)
//   wl:(2048,1024) bl:(1024)  out:(8192,1024) f32
//
// feat[o,i,j] = b2[o] + S1[o]*(i,j odd) + Z[o,a,b]*((i,j) in {3,7}^2)
// P (8192x2048) = pooled; out = leakyrelu(P @ wl + bl)
// Big GEMM via mma.sync bf16 3-term split (compute_103-safe, no tcgen05).
// ---------------------------------------------------------------------------

#define NSAMP 8192
#define SPB   8

__device__ float g_W[512 * 128];
__device__ float g_S1[128];
__device__ unsigned short g_Phi[(size_t)NSAMP * 2048];
__device__ unsigned short g_Plo[(size_t)NSAMP * 2048];
__device__ unsigned short g_WThi[(size_t)1024 * 2048];   // wl^T hi  [n][k]
__device__ unsigned short g_WTlo[(size_t)1024 * 2048];   // wl^T lo  [n][k]

#define SWZ128(off) ((off) ^ (((off) >> 3) & 0x70))

__device__ __forceinline__ void cp16(uint32_t dst, const void* src) {
    asm volatile("cp.async.cg.shared.global [%0], [%1], 16;"
                 :: "r"(dst), "l"(__cvta_generic_to_global(src)) : "memory");
}
__device__ __forceinline__ void ldm_x4(uint32_t addr, uint32_t& r0, uint32_t& r1,
                                       uint32_t& r2, uint32_t& r3) {
    asm volatile("ldmatrix.sync.aligned.m8n8.x4.shared.b16 {%0,%1,%2,%3}, [%4];"
                 : "=r"(r0), "=r"(r1), "=r"(r2), "=r"(r3) : "r"(addr));
}
__device__ __forceinline__ void mma16816(float& d0, float& d1, float& d2, float& d3,
                                         uint32_t a0, uint32_t a1, uint32_t a2,
                                         uint32_t a3, uint32_t b0, uint32_t b1) {
    asm volatile("mma.sync.aligned.m16n8k16.row.col.f32.bf16.bf16.f32 "
                 "{%0,%1,%2,%3}, {%4,%5,%6,%7}, {%8,%9}, {%0,%1,%2,%3};"
                 : "+f"(d0), "+f"(d1), "+f"(d2), "+f"(d3)
                 : "r"(a0), "r"(a1), "r"(a2), "r"(a3), "r"(b0), "r"(b1));
}

// ---------------------------------------------------------------------------
// Kernel 1: W = w1 @ w2, S1 = b1 @ w2
// ---------------------------------------------------------------------------
__global__ __launch_bounds__(128) void prep_kernel(const float* __restrict__ w1,
                                                   const float* __restrict__ b1,
                                                   const float* __restrict__ w2) {
    __shared__ float w1s[8][256];
    const int o = threadIdx.x;
    const int b = blockIdx.x;
    if (b < 64) {
        const float* src = w1 + b * 8 * 256;
        for (int i = o; i < 2048; i += 128) ((float*)w1s)[i] = src[i];
        __syncthreads();
        float acc[8];
        #pragma unroll
        for (int r = 0; r < 8; ++r) acc[r] = 0.f;
        for (int c = 0; c < 256; ++c) {
            const float wv = w2[c * 128 + o];
            #pragma unroll
            for (int r = 0; r < 8; ++r) acc[r] = fmaf(w1s[r][c], wv, acc[r]);
        }
        #pragma unroll
        for (int r = 0; r < 8; ++r) g_W[(b * 8 + r) * 128 + o] = acc[r];
    } else {
        float acc = 0.f;
        for (int c = 0; c < 256; ++c) acc = fmaf(b1[c], w2[c * 128 + o], acc);
        g_S1[o] = acc;
    }
}

// ---------------------------------------------------------------------------
// Kernel 1b: transpose + bf16-split wl -> g_WThi/g_WTlo  [n][k]
// ---------------------------------------------------------------------------
__global__ __launch_bounds__(256) void wsplit_kernel(const float* __restrict__ wl) {
    __shared__ float t[32][33];
    const int n0 = blockIdx.x * 32, k0 = blockIdx.y * 32;
    const int tx = threadIdx.x, ty = threadIdx.y;   // 32 x 8
    #pragma unroll
    for (int j = 0; j < 4; ++j)
        t[ty + j * 8][tx] = wl[(size_t)(k0 + ty + j * 8) * 1024 + n0 + tx];
    __syncthreads();
    #pragma unroll
    for (int j = 0; j < 4; ++j) {
        const int n = n0 + ty + j * 8, k = k0 + tx;
        const float v = t[tx][ty + j * 8];
        const __nv_bfloat16 h = __float2bfloat16(v);
        const __nv_bfloat16 l = __float2bfloat16(v - __bfloat162float(h));
        g_WThi[(size_t)n * 2048 + k] = __bfloat16_as_ushort(h);
        g_WTlo[(size_t)n * 2048 + k] = __bfloat16_as_ushort(l);
    }
}

// ---------------------------------------------------------------------------
// Kernel 2: per-sample Z + categorized max-pool -> bf16-split P rows
// ---------------------------------------------------------------------------
__global__ __launch_bounds__(128) void pool_kernel(const float* __restrict__ base,
                                                   const int* __restrict__ rois,
                                                   const float* __restrict__ b2) {
    __shared__ float4 xs[SPB][512];
    const int n0 = blockIdx.x * SPB;
    const int o  = threadIdx.x;

    for (int s = 0; s < SPB; ++s) {
        const float4* x4 = (const float4*)(base + (size_t)(n0 + s) * 8192);
        float2* dst = (float2*)xs[s];
        for (int j = o; j < 1024; j += 128) {
            const int k = j >> 1;
            const int q = 1 + (j & 1);
            float4 v = x4[k * 4 + q];
            dst[j] = make_float2(v.y, v.z);
        }
    }
    __syncthreads();

    float4 acc[SPB];
    #pragma unroll
    for (int s = 0; s < SPB; ++s) acc[s] = make_float4(0.f, 0.f, 0.f, 0.f);

    for (int k = 0; k < 512; ++k) {
        const float w = g_W[k * 128 + o];
        #pragma unroll
        for (int s = 0; s < SPB; ++s) {
            float4 xv = xs[s][k];
            acc[s].x = fmaf(xv.x, w, acc[s].x);
            acc[s].y = fmaf(xv.y, w, acc[s].y);
            acc[s].z = fmaf(xv.z, w, acc[s].z);
            acc[s].w = fmaf(xv.w, w, acc[s].w);
        }
    }

    const float b2o = b2[o];
    const float s1o = g_S1[o];

    for (int s = 0; s < SPB; ++s) {
        const int n = n0 + s;
        int4 rr = ((const int4*)rois)[n];
        int y0 = rr.x, x0 = rr.y;
        const int h = rr.z - rr.x, w = rr.w - rr.y;
        const bool inb = (rr.x >= 0 && rr.x < 11 && rr.y >= 0 && rr.y < 11 &&
                          rr.z >= 0 && rr.z < 11 && rr.w >= 0 && rr.w < 11);
        int cat;
        if      (inb && h == 4 && w == 4) cat = 0;
        else if (inb && h == 8 && w == 8) cat = 1;
        else if (inb && h == 4 && w == 8) cat = 2;
        else if (inb && h == 6 && w == 8) cat = 3;
        else { cat = 4; y0 = 1; x0 = 1; }

        const float z00 = acc[s].x, z01 = acc[s].y, z10 = acc[s].z, z11 = acc[s].w;
        auto feval = [&](int i, int j) -> float {
            float v = b2o;
            if ((i & 1) && (j & 1)) {
                v += s1o;
                const bool ia = (i == 3) || (i == 7);
                const bool ja = (j == 3) || (j == 7);
                if (ia && ja)
                    v += (i == 3) ? ((j == 3) ? z00 : z01)
                                  : ((j == 3) ? z10 : z11);
            }
            return v;
        };

        float cell[16];
        if (cat == 0) {
            for (int u = 0; u < 4; ++u)
                for (int v = 0; v < 4; ++v)
                    cell[u * 4 + v] = feval(y0 + u, x0 + v);
        } else if (cat == 1) {
            for (int u = 0; u < 4; ++u)
                for (int v = 0; v < 4; ++v) {
                    const int i0 = y0 + 2 * u, j0 = x0 + 2 * v;
                    cell[u * 4 + v] =
                        fmaxf(fmaxf(feval(i0, j0),     feval(i0, j0 + 1)),
                              fmaxf(feval(i0 + 1, j0), feval(i0 + 1, j0 + 1)));
                }
        } else if (cat == 2) {
            for (int u = 0; u < 4; ++u)
                for (int v = 0; v < 4; ++v) {
                    const int j0 = x0 + 2 * v;
                    cell[u * 4 + v] = fmaxf(feval(y0 + u, j0), feval(y0 + u, j0 + 1));
                }
        } else if (cat == 3) {
            for (int u = 0; u < 4; ++u)
                for (int v = 0; v < 4; ++v) {
                    const int j0 = x0 + 2 * v;
                    float m = -3.402823466e38f;
                    const int r0 = 2 * u - 1, r1 = 2 * u;
                    if (r0 >= 0) m = fmaxf(feval(y0 + r0, j0), feval(y0 + r0, j0 + 1));
                    if (r1 < 6)  m = fmaxf(m, fmaxf(feval(y0 + r1, j0),
                                                    feval(y0 + r1, j0 + 1)));
                    cell[u * 4 + v] = m;
                }
        } else {
            for (int u = 0; u < 4; ++u)
                for (int v = 0; v < 4; ++v) {
                    float m = -3.402823466e38f;
                    for (int di = 0; di < 3; ++di)
                        for (int dj = 0; dj < 3; ++dj)
                            m = fmaxf(m, feval(1 + 2 * u + di, 1 + 2 * v + dj));
                    cell[u * 4 + v] = m;
                }
        }

        __align__(16) unsigned short hi16[16];
        __align__(16) unsigned short lo16[16];
        #pragma unroll
        for (int i = 0; i < 16; ++i) {
            const float v = cell[i];
            const __nv_bfloat16 hb = __float2bfloat16(v);
            hi16[i] = __bfloat16_as_ushort(hb);
            lo16[i] = __bfloat16_as_ushort(__float2bfloat16(v - __bfloat162float(hb)));
        }
        uint4* ph = (uint4*)&g_Phi[(size_t)n * 2048 + o * 16];
        uint4* pl = (uint4*)&g_Plo[(size_t)n * 2048 + o * 16];
        ph[0] = ((uint4*)hi16)[0]; ph[1] = ((uint4*)hi16)[1];
        pl[0] = ((uint4*)lo16)[0]; pl[1] = ((uint4*)lo16)[1];
    }
}

// ---------------------------------------------------------------------------
// Kernel 3: mma.sync bf16-split GEMM: out = leakyrelu(P @ wl + bl)
// BM=128, BN=128, BK=64 bf16. 8 warps, warp tile 64x32.
// SMEM per stage: A(hi+lo) 32KB + B(hi+lo) 32KB = 64KB; double buffer 128KB.
// ---------------------------------------------------------------------------
#define BKB        64
#define NCHUNK     (2048 / BKB)
#define A_SPLIT    16384u
#define B_OFF      32768u
#define STAGE_SZ   65536u
#define GEMM_SMEM  (2u * STAGE_SZ)

__device__ __forceinline__ void load_chunk(uint32_t sbase, int bm, int bn,
                                           int k0, int tid) {
    #pragma unroll
    for (int it = 0; it < 16; ++it) {
        const int g = tid + it * 256;            // 0..4095
        const int isB   = g >> 11;               // 0: A, 1: B
        const int gg    = g & 2047;
        const int split = gg >> 10;              // 0: hi, 1: lo
        const int e     = gg & 1023;
        const int r     = e >> 3;                // 0..127 rows
        const int c     = e & 7;                 // 8 x 16B per 128B row
        const uint32_t dst = sbase + (isB ? B_OFF : 0u) + split * A_SPLIT
                           + SWZ128((uint32_t)(r * 128 + c * 16));
        const unsigned short* src =
            isB ? ((split ? g_WTlo : g_WThi) + (size_t)(bn + r) * 2048 + k0 + c * 8)
                : ((split ? g_Plo  : g_Phi)  + (size_t)(bm + r) * 2048 + k0 + c * 8);
        cp16(dst, src);
    }
}

__global__ __launch_bounds__(256, 1) void gemm3_kernel(const float* __restrict__ bias,
                                                       float* __restrict__ out) {
    extern __shared__ __align__(1024) char smem[];
    const uint32_t sb = (uint32_t)__cvta_generic_to_shared(smem);
    const int tid  = threadIdx.x;
    const int wid  = tid >> 5, lane = tid & 31;
    const int bn   = blockIdx.x * 128;
    const int bm   = blockIdx.y * 128;
    const int wm   = (wid >> 2) * 64;   // 2 warp-rows of 64
    const int wn   = (wid & 3) * 32;    // 4 warp-cols of 32

    float acc[4][4][4];
    #pragma unroll
    for (int i = 0; i < 4; ++i)
        #pragma unroll
        for (int j = 0; j < 4; ++j)
            #pragma unroll
            for (int q = 0; q < 4; ++q) acc[i][j][q] = 0.f;

    // ldmatrix per-lane row/col-group
    const int lrow = lane & 15;          // row within 16
    const int lcg  = (lane >> 4) * 16;   // byte col group (0 or 16)

    load_chunk(sb, bm, bn, 0, tid);
    asm volatile("cp.async.commit_group;" ::: "memory");
    asm volatile("cp.async.wait_group 0;" ::: "memory");
    __syncthreads();

    for (int c = 0; c < NCHUNK; ++c) {
        const uint32_t cur = sb + (uint32_t)(c & 1) * STAGE_SZ;
        const uint32_t nxt = sb + (uint32_t)((c & 1) ^ 1) * STAGE_SZ;
        if (c + 1 < NCHUNK) {
            load_chunk(nxt, bm, bn, (c + 1) * BKB, tid);
            asm volatile("cp.async.commit_group;" ::: "memory");
        }

        #pragma unroll
        for (int ks = 0; ks < 4; ++ks) {
            const int kb = ks * 32 + lcg;     // byte offset into 128B row
            uint32_t ah[4][4], al[4][4], bh[4][2], bl[4][2];
            #pragma unroll
            for (int mt = 0; mt < 4; ++mt) {
                const uint32_t off = (uint32_t)((wm + mt * 16 + lrow) * 128 + kb);
                ldm_x4(cur + SWZ128(off),
                       ah[mt][0], ah[mt][1], ah[mt][2], ah[mt][3]);
                ldm_x4(cur + A_SPLIT + SWZ128(off),
                       al[mt][0], al[mt][1], al[mt][2], al[mt][3]);
            }
            #pragma unroll
            for (int q = 0; q < 2; ++q) {     // two n16 groups
                const uint32_t off = (uint32_t)((wn + q * 16 + lrow) * 128 + kb);
                uint32_t r0, r1, r2, r3;
                ldm_x4(cur + B_OFF + SWZ128(off), r0, r1, r2, r3);
                bh[2 * q][0] = r0; bh[2 * q][1] = r2;
                bh[2 * q + 1][0] = r1; bh[2 * q + 1][1] = r3;
                ldm_x4(cur + B_OFF + A_SPLIT + SWZ128(off), r0, r1, r2, r3);
                bl[2 * q][0] = r0; bl[2 * q][1] = r2;
                bl[2 * q + 1][0] = r1; bl[2 * q + 1][1] = r3;
            }
            #pragma unroll
            for (int mt = 0; mt < 4; ++mt)
                #pragma unroll
                for (int nt = 0; nt < 4; ++nt) {
                    mma16816(acc[mt][nt][0], acc[mt][nt][1],
                             acc[mt][nt][2], acc[mt][nt][3],
                             ah[mt][0], ah[mt][1], ah[mt][2], ah[mt][3],
                             bh[nt][0], bh[nt][1]);
                    mma16816(acc[mt][nt][0], acc[mt][nt][1],
                             acc[mt][nt][2], acc[mt][nt][3],
                             ah[mt][0], ah[mt][1], ah[mt][2], ah[mt][3],
                             bl[nt][0], bl[nt][1]);
                    mma16816(acc[mt][nt][0], acc[mt][nt][1],
                             acc[mt][nt][2], acc[mt][nt][3],
                             al[mt][0], al[mt][1], al[mt][2], al[mt][3],
                             bh[nt][0], bh[nt][1]);
                }
        }

        if (c + 1 < NCHUNK)
            asm volatile("cp.async.wait_group 0;" ::: "memory");
        __syncthreads();
    }

    // epilogue: d-frag mapping (row = lane>>2 [+8], col = (lane&3)*2)
    const int er = lane >> 2, ec = (lane & 3) * 2;
    #pragma unroll
    for (int mt = 0; mt < 4; ++mt) {
        #pragma unroll
        for (int nt = 0; nt < 4; ++nt) {
            const int n = bn + wn + nt * 8 + ec;
            const float bv0 = bias[n], bv1 = bias[n + 1];
            #pragma unroll
            for (int half = 0; half < 2; ++half) {
                const int m = bm + wm + mt * 16 + er + half * 8;
                float h0 = acc[mt][nt][half * 2 + 0] + bv0;
                float h1 = acc[mt][nt][half * 2 + 1] + bv1;
                float2 o2;
                o2.x = h0 > 0.f ? h0 : 0.01f * h0;
                o2.y = h1 > 0.f ? h1 : 0.01f * h1;
                *(float2*)&out[(size_t)m * 1024 + n] = o2;
            }
        }
    }
}

// ---------------------------------------------------------------------------
extern "C" void kernel_launch(void* const* d_in, const int* in_sizes, int n_in,
                              void* d_out, int out_size) {
    const float* base = (const float*)d_in[0];
    const int*   rois = (const int*)d_in[1];
    const float* w1   = (const float*)d_in[2];
    const float* b1   = (const float*)d_in[3];
    const float* w2   = (const float*)d_in[4];
    const float* b2   = (const float*)d_in[5];
    const float* wl   = (const float*)d_in[6];
    const float* bl   = (const float*)d_in[7];
    float* out = (float*)d_out;

    static int smem_set = 0;
    if (!smem_set) {
        cudaFuncSetAttribute(gemm3_kernel, cudaFuncAttributeMaxDynamicSharedMemorySize,
                             GEMM_SMEM);
        smem_set = 1;
    }

    prep_kernel<<<65, 128>>>(w1, b1, w2);
    wsplit_kernel<<<dim3(32, 64), dim3(32, 8)>>>(wl);
    pool_kernel<<<NSAMP / SPB, 128>>>(base, rois, b2);
    gemm3_kernel<<<dim3(1024 / 128, NSAMP / 128), 256, GEMM_SMEM>>>(bl, out);
}

// round 4
// speedup vs baseline: 2.7065x; 1.4698x over previous
#include <cuda_runtime.h>
#include <cuda_bf16.h>
#include <math.h>
#include <stdint.h>

// ---------------------------------------------------------------------------
//   base_feat: (32,256,512,4,4) f32 -> 8192 samples of (512,16)
//   rois:(8192,4) i32  w1:(512,256) b1:(256) w2:(256,128) b2:(128)
//   wl:(2048,1024) bl:(1024)  out:(8192,1024) f32
//
// feat[o,i,j] = b2[o] + S1[o]*(i,j odd) + Z[o,a,b]*((i,j) in {3,7}^2)
// Z = X(32768x512) @ W(512x128) done with mma.sync bf16 3-term split,
// pool fused into zgemm epilogue; final GEMM (P @ wl) same bf16-split mma.
// ---------------------------------------------------------------------------

#define NSAMP 8192

__device__ float g_S1[128];
__device__ unsigned short g_Xhi[(size_t)NSAMP * 4 * 512];   // [m=4n+c][k]
__device__ unsigned short g_Xlo[(size_t)NSAMP * 4 * 512];
__device__ unsigned short g_WZhi[128 * 512];                // W^T [o][k]
__device__ unsigned short g_WZlo[128 * 512];
__device__ unsigned short g_Phi[(size_t)NSAMP * 2048];      // P hi [n][o*16+cell]
__device__ unsigned short g_Plo[(size_t)NSAMP * 2048];
__device__ unsigned short g_WThi[(size_t)1024 * 2048];      // wl^T [nn][k]
__device__ unsigned short g_WTlo[(size_t)1024 * 2048];

#define SWZ128(off) ((off) ^ (((off) >> 3) & 0x70))

__device__ __forceinline__ void cp16(uint32_t dst, const void* src) {
    asm volatile("cp.async.cg.shared.global [%0], [%1], 16;"
                 :: "r"(dst), "l"(__cvta_generic_to_global(src)) : "memory");
}
__device__ __forceinline__ void ldm_x4(uint32_t addr, uint32_t& r0, uint32_t& r1,
                                       uint32_t& r2, uint32_t& r3) {
    asm volatile("ldmatrix.sync.aligned.m8n8.x4.shared.b16 {%0,%1,%2,%3}, [%4];"
                 : "=r"(r0), "=r"(r1), "=r"(r2), "=r"(r3) : "r"(addr));
}
__device__ __forceinline__ void mma16816(float& d0, float& d1, float& d2, float& d3,
                                         uint32_t a0, uint32_t a1, uint32_t a2,
                                         uint32_t a3, uint32_t b0, uint32_t b1) {
    asm volatile("mma.sync.aligned.m16n8k16.row.col.f32.bf16.bf16.f32 "
                 "{%0,%1,%2,%3}, {%4,%5,%6,%7}, {%8,%9}, {%0,%1,%2,%3};"
                 : "+f"(d0), "+f"(d1), "+f"(d2), "+f"(d3)
                 : "r"(a0), "r"(a1), "r"(a2), "r"(a3), "r"(b0), "r"(b1));
}

// shared GEMM building blocks -----------------------------------------------
#define A_SPLIT    16384u
#define B_OFF      32768u
#define STAGE_SZ   65536u

__device__ __forceinline__ void load_chunk_g(
    uint32_t sbase,
    const unsigned short* __restrict__ Ahi, const unsigned short* __restrict__ Alo,
    const unsigned short* __restrict__ Bhi, const unsigned short* __restrict__ Blo,
    int arow0, int brow0, size_t stride, int k0, int tid) {
    #pragma unroll
    for (int it = 0; it < 16; ++it) {
        const int g = tid + it * 256;            // 0..4095
        const int isB   = g >> 11;
        const int gg    = g & 2047;
        const int split = gg >> 10;
        const int e     = gg & 1023;
        const int r     = e >> 3;
        const int c     = e & 7;
        const uint32_t dst = sbase + (isB ? B_OFF : 0u) + split * A_SPLIT
                           + SWZ128((uint32_t)(r * 128 + c * 16));
        const unsigned short* src =
            isB ? ((split ? Blo : Bhi) + (size_t)(brow0 + r) * stride + k0 + c * 8)
                : ((split ? Alo : Ahi) + (size_t)(arow0 + r) * stride + k0 + c * 8);
        cp16(dst, src);
    }
}

__device__ __forceinline__ void mma_block(uint32_t cur, float acc[4][4][4],
                                          int wm, int wn, int lane) {
    const int lrow = lane & 15;
    const int lcg  = (lane >> 4) * 16;
    #pragma unroll
    for (int ks = 0; ks < 4; ++ks) {
        const int kb = ks * 32 + lcg;
        uint32_t ah[4][4], al[4][4], bh[4][2], bl[4][2];
        #pragma unroll
        for (int mt = 0; mt < 4; ++mt) {
            const uint32_t off = (uint32_t)((wm + mt * 16 + lrow) * 128 + kb);
            ldm_x4(cur + SWZ128(off), ah[mt][0], ah[mt][1], ah[mt][2], ah[mt][3]);
            ldm_x4(cur + A_SPLIT + SWZ128(off),
                   al[mt][0], al[mt][1], al[mt][2], al[mt][3]);
        }
        #pragma unroll
        for (int q = 0; q < 2; ++q) {
            const uint32_t off = (uint32_t)((wn + q * 16 + lrow) * 128 + kb);
            uint32_t r0, r1, r2, r3;
            ldm_x4(cur + B_OFF + SWZ128(off), r0, r1, r2, r3);
            bh[2 * q][0] = r0;     bh[2 * q][1] = r2;
            bh[2 * q + 1][0] = r1; bh[2 * q + 1][1] = r3;
            ldm_x4(cur + B_OFF + A_SPLIT + SWZ128(off), r0, r1, r2, r3);
            bl[2 * q][0] = r0;     bl[2 * q][1] = r2;
            bl[2 * q + 1][0] = r1; bl[2 * q + 1][1] = r3;
        }
        #pragma unroll
        for (int mt = 0; mt < 4; ++mt)
            #pragma unroll
            for (int nt = 0; nt < 4; ++nt) {
                mma16816(acc[mt][nt][0], acc[mt][nt][1],
                         acc[mt][nt][2], acc[mt][nt][3],
                         ah[mt][0], ah[mt][1], ah[mt][2], ah[mt][3],
                         bh[nt][0], bh[nt][1]);
                mma16816(acc[mt][nt][0], acc[mt][nt][1],
                         acc[mt][nt][2], acc[mt][nt][3],
                         ah[mt][0], ah[mt][1], ah[mt][2], ah[mt][3],
                         bl[nt][0], bl[nt][1]);
                mma16816(acc[mt][nt][0], acc[mt][nt][1],
                         acc[mt][nt][2], acc[mt][nt][3],
                         al[mt][0], al[mt][1], al[mt][2], al[mt][3],
                         bh[nt][0], bh[nt][1]);
            }
    }
}

// ---------------------------------------------------------------------------
// Kernel 1: W = w1 @ w2 -> bf16 split transposed [o][k];  S1 = b1 @ w2 (f32)
// ---------------------------------------------------------------------------
__global__ __launch_bounds__(128) void prep_kernel(const float* __restrict__ w1,
                                                   const float* __restrict__ b1,
                                                   const float* __restrict__ w2) {
    __shared__ float w1s[8][256];
    const int o = threadIdx.x;
    const int b = blockIdx.x;
    if (b < 64) {
        const float* src = w1 + b * 8 * 256;
        for (int i = o; i < 2048; i += 128) ((float*)w1s)[i] = src[i];
        __syncthreads();
        float acc[8];
        #pragma unroll
        for (int r = 0; r < 8; ++r) acc[r] = 0.f;
        #pragma unroll 4
        for (int c = 0; c < 256; ++c) {
            const float wv = w2[c * 128 + o];
            #pragma unroll
            for (int r = 0; r < 8; ++r) acc[r] = fmaf(w1s[r][c], wv, acc[r]);
        }
        #pragma unroll
        for (int r = 0; r < 8; ++r) {
            const int k = b * 8 + r;
            const float v = acc[r];
            const __nv_bfloat16 h = __float2bfloat16(v);
            g_WZhi[o * 512 + k] = __bfloat16_as_ushort(h);
            g_WZlo[o * 512 + k] =
                __bfloat16_as_ushort(__float2bfloat16(v - __bfloat162float(h)));
        }
    } else {
        float acc = 0.f;
        for (int c = 0; c < 256; ++c) acc = fmaf(b1[c], w2[c * 128 + o], acc);
        g_S1[o] = acc;
    }
}

// ---------------------------------------------------------------------------
// Kernel 1b: transpose + bf16-split wl -> g_WThi/g_WTlo [nn][k]
// ---------------------------------------------------------------------------
__global__ __launch_bounds__(256) void wsplit_kernel(const float* __restrict__ wl) {
    __shared__ float t[32][33];
    const int n0 = blockIdx.x * 32, k0 = blockIdx.y * 32;
    const int tx = threadIdx.x, ty = threadIdx.y;   // 32 x 8
    #pragma unroll
    for (int j = 0; j < 4; ++j)
        t[ty + j * 8][tx] = wl[(size_t)(k0 + ty + j * 8) * 1024 + n0 + tx];
    __syncthreads();
    #pragma unroll
    for (int j = 0; j < 4; ++j) {
        const int n = n0 + ty + j * 8, k = k0 + tx;
        const float v = t[tx][ty + j * 8];
        const __nv_bfloat16 h = __float2bfloat16(v);
        const __nv_bfloat16 l = __float2bfloat16(v - __bfloat162float(h));
        g_WThi[(size_t)n * 2048 + k] = __bfloat16_as_ushort(h);
        g_WTlo[(size_t)n * 2048 + k] = __bfloat16_as_ushort(l);
    }
}

// ---------------------------------------------------------------------------
// Kernel 1c: extract 2x2 centers of base_feat -> bf16 split X [m=4n+c][k]
// ---------------------------------------------------------------------------
__global__ __launch_bounds__(256) void xsplit_kernel(const float* __restrict__ base) {
    const int n0 = blockIdx.x * 8;
    const int tid = threadIdx.x;
    for (int s = 0; s < 8; ++s) {
        const int n = n0 + s;
        const float4* src = (const float4*)(base + (size_t)n * 8192);
        #pragma unroll
        for (int i = 0; i < 2; ++i) {
            const int k = tid + i * 256;
            const float4 v1 = src[k * 4 + 1];   // f4..f7 -> f5,f6 = c0,c1
            const float4 v2 = src[k * 4 + 2];   // f8..f11 -> f9,f10 = c2,c3
            float a[4] = {v1.y, v1.z, v2.y, v2.z};
            const size_t m0 = (size_t)(4 * n) * 512 + k;
            #pragma unroll
            for (int c = 0; c < 4; ++c) {
                const __nv_bfloat16 h = __float2bfloat16(a[c]);
                g_Xhi[m0 + c * 512] = __bfloat16_as_ushort(h);
                g_Xlo[m0 + c * 512] =
                    __bfloat16_as_ushort(__float2bfloat16(a[c] - __bfloat162float(h)));
            }
        }
    }
}

// ---------------------------------------------------------------------------
// Kernel 2: zgemm (Z = X @ W^T) with fused categorized max-pool epilogue.
// BM=128 (32 samples), BN=128, K=512, BK=64, double-buffered.
// Dynamic smem: 2 stages (128KB) + rois/b2/S1 (1.5KB). Z staged to smem f32.
// ---------------------------------------------------------------------------
#define ZCHUNK    8
#define ZS_STRIDE 136
#define SM_ROIS   (2u * STAGE_SZ)
#define SM_B2     (SM_ROIS + 512u)
#define SM_S1     (SM_B2 + 512u)
#define ZG_SMEM   (SM_S1 + 512u)

__global__ __launch_bounds__(256, 1) void zgemm_kernel(const int* __restrict__ rois,
                                                       const float* __restrict__ b2) {
    extern __shared__ __align__(1024) char smem[];
    const uint32_t sb = (uint32_t)__cvta_generic_to_shared(smem);
    const int tid  = threadIdx.x;
    const int wid  = tid >> 5, lane = tid & 31;
    const int n0   = blockIdx.x * 32;
    const int bm   = blockIdx.x * 128;
    const int wm   = (wid >> 2) * 64;
    const int wn   = (wid & 3) * 32;

    int4*  rois_s = (int4*)(smem + SM_ROIS);
    float* b2s    = (float*)(smem + SM_B2);
    float* s1s    = (float*)(smem + SM_S1);
    if (tid < 32) rois_s[tid] = ((const int4*)rois)[n0 + tid];
    if (tid >= 128) { b2s[tid - 128] = b2[tid - 128]; s1s[tid - 128] = g_S1[tid - 128]; }

    float acc[4][4][4];
    #pragma unroll
    for (int i = 0; i < 4; ++i)
        #pragma unroll
        for (int j = 0; j < 4; ++j)
            #pragma unroll
            for (int q = 0; q < 4; ++q) acc[i][j][q] = 0.f;

    load_chunk_g(sb, g_Xhi, g_Xlo, g_WZhi, g_WZlo, bm, 0, 512, 0, tid);
    asm volatile("cp.async.commit_group;" ::: "memory");
    asm volatile("cp.async.wait_group 0;" ::: "memory");
    __syncthreads();

    for (int c = 0; c < ZCHUNK; ++c) {
        const uint32_t cur = sb + (uint32_t)(c & 1) * STAGE_SZ;
        const uint32_t nxt = sb + (uint32_t)((c & 1) ^ 1) * STAGE_SZ;
        if (c + 1 < ZCHUNK) {
            load_chunk_g(nxt, g_Xhi, g_Xlo, g_WZhi, g_WZlo, bm, 0, 512,
                         (c + 1) * 64, tid);
            asm volatile("cp.async.commit_group;" ::: "memory");
        }
        mma_block(cur, acc, wm, wn, lane);
        if (c + 1 < ZCHUNK)
            asm volatile("cp.async.wait_group 0;" ::: "memory");
        __syncthreads();
    }

    // stage Z tile to smem (f32, padded stride)
    float* zs = (float*)smem;
    const int er = lane >> 2, ec = (lane & 3) * 2;
    #pragma unroll
    for (int mt = 0; mt < 4; ++mt)
        #pragma unroll
        for (int nt = 0; nt < 4; ++nt)
            #pragma unroll
            for (int half = 0; half < 2; ++half) {
                const int row = wm + mt * 16 + er + half * 8;
                const int col = wn + nt * 8 + ec;
                *(float2*)&zs[row * ZS_STRIDE + col] =
                    make_float2(acc[mt][nt][half * 2 + 0], acc[mt][nt][half * 2 + 1]);
            }
    __syncthreads();

    // fused pool: 32 samples x 128 channels, 16 (n,o) pairs per thread
    #pragma unroll 1
    for (int it = 0; it < 16; ++it) {
        const int pair = tid + it * 256;
        const int n = pair >> 7, o = pair & 127;
        const int4 rr = rois_s[n];
        const float b2o = b2s[o], s1o = s1s[o];
        const float z00 = zs[(4 * n + 0) * ZS_STRIDE + o];
        const float z01 = zs[(4 * n + 1) * ZS_STRIDE + o];
        const float z10 = zs[(4 * n + 2) * ZS_STRIDE + o];
        const float z11 = zs[(4 * n + 3) * ZS_STRIDE + o];

        int y0 = rr.x, x0 = rr.y;
        const int h = rr.z - rr.x, w = rr.w - rr.y;
        const bool inb = (rr.x >= 0 && rr.x < 11 && rr.y >= 0 && rr.y < 11 &&
                          rr.z >= 0 && rr.z < 11 && rr.w >= 0 && rr.w < 11);
        int cat;
        if      (inb && h == 4 && w == 4) cat = 0;
        else if (inb && h == 8 && w == 8) cat = 1;
        else if (inb && h == 4 && w == 8) cat = 2;
        else if (inb && h == 6 && w == 8) cat = 3;
        else { cat = 4; y0 = 1; x0 = 1; }

        auto feval = [&](int i, int j) -> float {
            float v = b2o;
            if ((i & 1) && (j & 1)) {
                v += s1o;
                const bool ia = (i == 3) || (i == 7);
                const bool ja = (j == 3) || (j == 7);
                if (ia && ja)
                    v += (i == 3) ? ((j == 3) ? z00 : z01)
                                  : ((j == 3) ? z10 : z11);
            }
            return v;
        };

        float cell[16];
        if (cat == 0) {
            for (int u = 0; u < 4; ++u)
                for (int v = 0; v < 4; ++v)
                    cell[u * 4 + v] = feval(y0 + u, x0 + v);
        } else if (cat == 1) {
            for (int u = 0; u < 4; ++u)
                for (int v = 0; v < 4; ++v) {
                    const int i0 = y0 + 2 * u, j0 = x0 + 2 * v;
                    cell[u * 4 + v] =
                        fmaxf(fmaxf(feval(i0, j0),     feval(i0, j0 + 1)),
                              fmaxf(feval(i0 + 1, j0), feval(i0 + 1, j0 + 1)));
                }
        } else if (cat == 2) {
            for (int u = 0; u < 4; ++u)
                for (int v = 0; v < 4; ++v) {
                    const int j0 = x0 + 2 * v;
                    cell[u * 4 + v] = fmaxf(feval(y0 + u, j0), feval(y0 + u, j0 + 1));
                }
        } else if (cat == 3) {
            for (int u = 0; u < 4; ++u)
                for (int v = 0; v < 4; ++v) {
                    const int j0 = x0 + 2 * v;
                    float m = -3.402823466e38f;
                    const int r0 = 2 * u - 1, r1 = 2 * u;
                    if (r0 >= 0) m = fmaxf(feval(y0 + r0, j0), feval(y0 + r0, j0 + 1));
                    if (r1 < 6)  m = fmaxf(m, fmaxf(feval(y0 + r1, j0),
                                                    feval(y0 + r1, j0 + 1)));
                    cell[u * 4 + v] = m;
                }
        } else {
            for (int u = 0; u < 4; ++u)
                for (int v = 0; v < 4; ++v) {
                    float m = -3.402823466e38f;
                    for (int di = 0; di < 3; ++di)
                        for (int dj = 0; dj < 3; ++dj)
                            m = fmaxf(m, feval(1 + 2 * u + di, 1 + 2 * v + dj));
                    cell[u * 4 + v] = m;
                }
        }

        __align__(16) unsigned short hi16[16];
        __align__(16) unsigned short lo16[16];
        #pragma unroll
        for (int i = 0; i < 16; ++i) {
            const float v = cell[i];
            const __nv_bfloat16 hb = __float2bfloat16(v);
            hi16[i] = __bfloat16_as_ushort(hb);
            lo16[i] = __bfloat16_as_ushort(__float2bfloat16(v - __bfloat162float(hb)));
        }
        uint4* ph = (uint4*)&g_Phi[(size_t)(n0 + n) * 2048 + o * 16];
        uint4* pl = (uint4*)&g_Plo[(size_t)(n0 + n) * 2048 + o * 16];
        ph[0] = ((uint4*)hi16)[0]; ph[1] = ((uint4*)hi16)[1];
        pl[0] = ((uint4*)lo16)[0]; pl[1] = ((uint4*)lo16)[1];
    }
}

// ---------------------------------------------------------------------------
// Kernel 3: out = leakyrelu(P @ wl + bl), mma.sync bf16 3-term split.
// BM=128, BN=128, BK=64, K=2048, double-buffered (128KB smem).
// ---------------------------------------------------------------------------
#define NCHUNK3    32
#define GEMM_SMEM  (2u * STAGE_SZ)

__global__ __launch_bounds__(256, 1) void gemm3_kernel(const float* __restrict__ bias,
                                                       float* __restrict__ out) {
    extern __shared__ __align__(1024) char smem[];
    const uint32_t sb = (uint32_t)__cvta_generic_to_shared(smem);
    const int tid  = threadIdx.x;
    const int wid  = tid >> 5, lane = tid & 31;
    const int bn   = blockIdx.x * 128;
    const int bm   = blockIdx.y * 128;
    const int wm   = (wid >> 2) * 64;
    const int wn   = (wid & 3) * 32;

    float acc[4][4][4];
    #pragma unroll
    for (int i = 0; i < 4; ++i)
        #pragma unroll
        for (int j = 0; j < 4; ++j)
            #pragma unroll
            for (int q = 0; q < 4; ++q) acc[i][j][q] = 0.f;

    load_chunk_g(sb, g_Phi, g_Plo, g_WThi, g_WTlo, bm, bn, 2048, 0, tid);
    asm volatile("cp.async.commit_group;" ::: "memory");
    asm volatile("cp.async.wait_group 0;" ::: "memory");
    __syncthreads();

    for (int c = 0; c < NCHUNK3; ++c) {
        const uint32_t cur = sb + (uint32_t)(c & 1) * STAGE_SZ;
        const uint32_t nxt = sb + (uint32_t)((c & 1) ^ 1) * STAGE_SZ;
        if (c + 1 < NCHUNK3) {
            load_chunk_g(nxt, g_Phi, g_Plo, g_WThi, g_WTlo, bm, bn, 2048,
                         (c + 1) * 64, tid);
            asm volatile("cp.async.commit_group;" ::: "memory");
        }
        mma_block(cur, acc, wm, wn, lane);
        if (c + 1 < NCHUNK3)
            asm volatile("cp.async.wait_group 0;" ::: "memory");
        __syncthreads();
    }

    const int er = lane >> 2, ec = (lane & 3) * 2;
    #pragma unroll
    for (int mt = 0; mt < 4; ++mt) {
        #pragma unroll
        for (int nt = 0; nt < 4; ++nt) {
            const int n = bn + wn + nt * 8 + ec;
            const float bv0 = bias[n], bv1 = bias[n + 1];
            #pragma unroll
            for (int half = 0; half < 2; ++half) {
                const int m = bm + wm + mt * 16 + er + half * 8;
                float h0 = acc[mt][nt][half * 2 + 0] + bv0;
                float h1 = acc[mt][nt][half * 2 + 1] + bv1;
                float2 o2;
                o2.x = h0 > 0.f ? h0 : 0.01f * h0;
                o2.y = h1 > 0.f ? h1 : 0.01f * h1;
                *(float2*)&out[(size_t)m * 1024 + n] = o2;
            }
        }
    }
}

// ---------------------------------------------------------------------------
extern "C" void kernel_launch(void* const* d_in, const int* in_sizes, int n_in,
                              void* d_out, int out_size) {
    const float* base = (const float*)d_in[0];
    const int*   rois = (const int*)d_in[1];
    const float* w1   = (const float*)d_in[2];
    const float* b1   = (const float*)d_in[3];
    const float* w2   = (const float*)d_in[4];
    const float* b2   = (const float*)d_in[5];
    const float* wl   = (const float*)d_in[6];
    const float* bl   = (const float*)d_in[7];
    float* out = (float*)d_out;

    cudaFuncSetAttribute(zgemm_kernel, cudaFuncAttributeMaxDynamicSharedMemorySize,
                         ZG_SMEM);
    cudaFuncSetAttribute(gemm3_kernel, cudaFuncAttributeMaxDynamicSharedMemorySize,
                         GEMM_SMEM);

    prep_kernel<<<65, 128>>>(w1, b1, w2);
    wsplit_kernel<<<dim3(32, 64), dim3(32, 8)>>>(wl);
    xsplit_kernel<<<NSAMP / 8, 256>>>(base);
    zgemm_kernel<<<NSAMP / 32, 256, ZG_SMEM>>>(rois, b2);
    gemm3_kernel<<<dim3(1024 / 128, NSAMP / 128), 256, GEMM_SMEM>>>(bl, out);
}

// round 5
// speedup vs baseline: 3.3951x; 1.2544x over previous
#include <cuda_runtime.h>
#include <cuda_bf16.h>
#include <math.h>
#include <stdint.h>

// ---------------------------------------------------------------------------
//   base_feat: (32,256,512,4,4) f32 -> 8192 samples of (512,16)
//   rois:(8192,4) i32  w1:(512,256) b1:(256) w2:(256,128) b2:(128)
//   wl:(2048,1024) bl:(1024)  out:(8192,1024) f32
//
// feat[o,i,j] = b2[o] + S1[o]*(i,j odd) + Z[o,a,b]*((i,j) in {3,7}^2)
// Z = X(32768x512) @ W^T(128x512) via 1xTF32 mma, pool fused in epilogue.
// out = leakyrelu(P(8192x2048) @ wl + bl) via 1xTF32 mma.
// All operand arrays pre-rounded to tf32 (cvt.rna) at producer time.
// ---------------------------------------------------------------------------

#define NSAMP 8192

__device__ float g_S1[128];
__device__ float g_X[(size_t)NSAMP * 4 * 512];   // [m=4n+c][k] tf32
__device__ float g_WZ[128 * 512];                // W^T [o][k]  tf32
__device__ float g_P[(size_t)NSAMP * 2048];      // P   [n][o*16+cell] tf32
__device__ float g_WT[(size_t)1024 * 2048];      // wl^T [nn][k] tf32

#define SWZ128(off) ((off) ^ (((off) >> 3) & 0x70))

__device__ __forceinline__ float to_tf32(float x) {
    float r;
    asm("cvt.rna.tf32.f32 %0, %1;" : "=f"(r) : "f"(x));
    return r;
}
__device__ __forceinline__ void cp16(uint32_t dst, const void* src) {
    asm volatile("cp.async.cg.shared.global [%0], [%1], 16;"
                 :: "r"(dst), "l"(__cvta_generic_to_global(src)) : "memory");
}
__device__ __forceinline__ void ldm_x4(uint32_t addr, uint32_t& r0, uint32_t& r1,
                                       uint32_t& r2, uint32_t& r3) {
    asm volatile("ldmatrix.sync.aligned.m8n8.x4.shared.b16 {%0,%1,%2,%3}, [%4];"
                 : "=r"(r0), "=r"(r1), "=r"(r2), "=r"(r3) : "r"(addr));
}
__device__ __forceinline__ void mma_tf32(float& d0, float& d1, float& d2, float& d3,
                                         uint32_t a0, uint32_t a1, uint32_t a2,
                                         uint32_t a3, uint32_t b0, uint32_t b1) {
    asm volatile("mma.sync.aligned.m16n8k8.row.col.f32.tf32.tf32.f32 "
                 "{%0,%1,%2,%3}, {%4,%5,%6,%7}, {%8,%9}, {%0,%1,%2,%3};"
                 : "+f"(d0), "+f"(d1), "+f"(d2), "+f"(d3)
                 : "r"(a0), "r"(a1), "r"(a2), "r"(a3), "r"(b0), "r"(b1));
}

// shared GEMM building blocks (BK = 64 fp32) --------------------------------
// Stage layout: A at 0, B at B_OFF. Each operand: 2 k-half subtiles of
// 16KB = [128 rows][128B], element (r,k): (k>>5)*16384 + r*128 + (k&31)*4.
#define KSUB       16384u
#define B_OFF      32768u
#define STAGE_SZ   65536u

__device__ __forceinline__ void load_chunk_g(
    uint32_t sbase,
    const float* __restrict__ A, const float* __restrict__ B,
    int arow0, int brow0, size_t strideA, size_t strideB, int k0, int tid) {
    #pragma unroll
    for (int it = 0; it < 16; ++it) {
        const int g = tid + it * 256;            // 0..4095 (16B units)
        const int isB = g >> 11;
        const int e   = g & 2047;
        const int r   = e >> 4;                  // 0..127 rows
        const int u   = e & 15;                  // 16 x 16B per 64-fp32 row
        const uint32_t dst = sbase + (isB ? B_OFF : 0u) + (uint32_t)(u >> 3) * KSUB
                           + SWZ128((uint32_t)(r * 128 + (u & 7) * 16));
        const float* src = isB ? (B + (size_t)(brow0 + r) * strideB + k0 + u * 4)
                               : (A + (size_t)(arow0 + r) * strideA + k0 + u * 4);
        cp16(dst, src);
    }
}

// 8 k-slices of 8; per warp per slice: 4 A ldmatrix + 2 B ldmatrix + 16 MMA.
__device__ __forceinline__ void mma_block(uint32_t cur, float acc[4][4][4],
                                          int wm, int wn, int lane) {
    const int r16  = lane & 15;
    const int h16  = (lane >> 4) * 16;   // 16B half selector
    #pragma unroll
    for (int ks = 0; ks < 8; ++ks) {
        const uint32_t abase = cur + (uint32_t)(ks >> 2) * KSUB;
        const uint32_t bbase = abase + B_OFF;
        const int kb = (ks & 3) * 32 + h16;
        uint32_t a[4][4], b[4][2];
        #pragma unroll
        for (int mt = 0; mt < 4; ++mt)
            ldm_x4(abase + SWZ128((uint32_t)((wm + mt * 16 + r16) * 128 + kb)),
                   a[mt][0], a[mt][1], a[mt][2], a[mt][3]);
        #pragma unroll
        for (int q = 0; q < 2; ++q) {
            uint32_t r0, r1, r2, r3;
            ldm_x4(bbase + SWZ128((uint32_t)((wn + q * 16 + r16) * 128 + kb)),
                   r0, r1, r2, r3);
            b[2 * q][0] = r0;     b[2 * q][1] = r2;
            b[2 * q + 1][0] = r1; b[2 * q + 1][1] = r3;
        }
        #pragma unroll
        for (int mt = 0; mt < 4; ++mt)
            #pragma unroll
            for (int nt = 0; nt < 4; ++nt)
                mma_tf32(acc[mt][nt][0], acc[mt][nt][1],
                         acc[mt][nt][2], acc[mt][nt][3],
                         a[mt][0], a[mt][1], a[mt][2], a[mt][3],
                         b[nt][0], b[nt][1]);
    }
}

// ---------------------------------------------------------------------------
// Kernel 1: W = w1 @ w2 -> tf32 [o][k];  S1 = b1 @ w2 (f32)
// ---------------------------------------------------------------------------
__global__ __launch_bounds__(128) void prep_kernel(const float* __restrict__ w1,
                                                   const float* __restrict__ b1,
                                                   const float* __restrict__ w2) {
    __shared__ float w1s[8][256];
    const int o = threadIdx.x;
    const int b = blockIdx.x;
    if (b < 64) {
        const float* src = w1 + b * 8 * 256;
        for (int i = o; i < 2048; i += 128) ((float*)w1s)[i] = src[i];
        __syncthreads();
        float acc[8];
        #pragma unroll
        for (int r = 0; r < 8; ++r) acc[r] = 0.f;
        #pragma unroll 4
        for (int c = 0; c < 256; ++c) {
            const float wv = w2[c * 128 + o];
            #pragma unroll
            for (int r = 0; r < 8; ++r) acc[r] = fmaf(w1s[r][c], wv, acc[r]);
        }
        #pragma unroll
        for (int r = 0; r < 8; ++r)
            g_WZ[o * 512 + b * 8 + r] = to_tf32(acc[r]);
    } else {
        float acc = 0.f;
        for (int c = 0; c < 256; ++c) acc = fmaf(b1[c], w2[c * 128 + o], acc);
        g_S1[o] = acc;
    }
}

// ---------------------------------------------------------------------------
// Kernel 1b: transpose wl -> g_WT [nn][k] tf32
// ---------------------------------------------------------------------------
__global__ __launch_bounds__(256) void wsplit_kernel(const float* __restrict__ wl) {
    __shared__ float t[32][33];
    const int n0 = blockIdx.x * 32, k0 = blockIdx.y * 32;
    const int tx = threadIdx.x, ty = threadIdx.y;   // 32 x 8
    #pragma unroll
    for (int j = 0; j < 4; ++j)
        t[ty + j * 8][tx] = wl[(size_t)(k0 + ty + j * 8) * 1024 + n0 + tx];
    __syncthreads();
    #pragma unroll
    for (int j = 0; j < 4; ++j)
        g_WT[(size_t)(n0 + ty + j * 8) * 2048 + k0 + tx] = to_tf32(t[tx][ty + j * 8]);
}

// ---------------------------------------------------------------------------
// Kernel 1c: extract 2x2 centers of base_feat -> tf32 X [m=4n+c][k]
// ---------------------------------------------------------------------------
__global__ __launch_bounds__(256) void xsplit_kernel(const float* __restrict__ base) {
    const int n0 = blockIdx.x * 8;
    const int tid = threadIdx.x;
    for (int s = 0; s < 8; ++s) {
        const int n = n0 + s;
        const float4* src = (const float4*)(base + (size_t)n * 8192);
        #pragma unroll
        for (int i = 0; i < 2; ++i) {
            const int k = tid + i * 256;
            const float4 v1 = src[k * 4 + 1];   // f5,f6 = centers 0,1
            const float4 v2 = src[k * 4 + 2];   // f9,f10 = centers 2,3
            const size_t m0 = (size_t)(4 * n) * 512 + k;
            g_X[m0 + 0 * 512] = to_tf32(v1.y);
            g_X[m0 + 1 * 512] = to_tf32(v1.z);
            g_X[m0 + 2 * 512] = to_tf32(v2.y);
            g_X[m0 + 3 * 512] = to_tf32(v2.z);
        }
    }
}

// ---------------------------------------------------------------------------
// Kernel 2: zgemm (Z = X @ W^T) with fused categorized max-pool epilogue.
// BM=128 (32 samples), BN=128, K=512, BK=64, double-buffered.
// ---------------------------------------------------------------------------
#define ZCHUNK    8
#define ZS_STRIDE 136
#define SM_ROIS   (2u * STAGE_SZ)
#define SM_B2     (SM_ROIS + 512u)
#define SM_S1     (SM_B2 + 512u)
#define ZG_SMEM   (SM_S1 + 512u)

__global__ __launch_bounds__(256, 1) void zgemm_kernel(const int* __restrict__ rois,
                                                       const float* __restrict__ b2) {
    extern __shared__ __align__(1024) char smem[];
    const uint32_t sb = (uint32_t)__cvta_generic_to_shared(smem);
    const int tid  = threadIdx.x;
    const int wid  = tid >> 5, lane = tid & 31;
    const int n0   = blockIdx.x * 32;
    const int bm   = blockIdx.x * 128;
    const int wm   = (wid >> 2) * 64;
    const int wn   = (wid & 3) * 32;

    int4*  rois_s = (int4*)(smem + SM_ROIS);
    float* b2s    = (float*)(smem + SM_B2);
    float* s1s    = (float*)(smem + SM_S1);
    if (tid < 32) rois_s[tid] = ((const int4*)rois)[n0 + tid];
    if (tid >= 128) { b2s[tid - 128] = b2[tid - 128]; s1s[tid - 128] = g_S1[tid - 128]; }

    float acc[4][4][4];
    #pragma unroll
    for (int i = 0; i < 4; ++i)
        #pragma unroll
        for (int j = 0; j < 4; ++j)
            #pragma unroll
            for (int q = 0; q < 4; ++q) acc[i][j][q] = 0.f;

    load_chunk_g(sb, g_X, g_WZ, bm, 0, 512, 512, 0, tid);
    asm volatile("cp.async.commit_group;" ::: "memory");
    asm volatile("cp.async.wait_group 0;" ::: "memory");
    __syncthreads();

    for (int c = 0; c < ZCHUNK; ++c) {
        const uint32_t cur = sb + (uint32_t)(c & 1) * STAGE_SZ;
        const uint32_t nxt = sb + (uint32_t)((c & 1) ^ 1) * STAGE_SZ;
        if (c + 1 < ZCHUNK) {
            load_chunk_g(nxt, g_X, g_WZ, bm, 0, 512, 512, (c + 1) * 64, tid);
            asm volatile("cp.async.commit_group;" ::: "memory");
        }
        mma_block(cur, acc, wm, wn, lane);
        if (c + 1 < ZCHUNK)
            asm volatile("cp.async.wait_group 0;" ::: "memory");
        __syncthreads();
    }

    // stage Z tile to smem (f32, padded stride)
    float* zs = (float*)smem;
    const int er = lane >> 2, ec = (lane & 3) * 2;
    #pragma unroll
    for (int mt = 0; mt < 4; ++mt)
        #pragma unroll
        for (int nt = 0; nt < 4; ++nt)
            #pragma unroll
            for (int half = 0; half < 2; ++half) {
                const int row = wm + mt * 16 + er + half * 8;
                const int col = wn + nt * 8 + ec;
                *(float2*)&zs[row * ZS_STRIDE + col] =
                    make_float2(acc[mt][nt][half * 2 + 0], acc[mt][nt][half * 2 + 1]);
            }
    __syncthreads();

    // fused pool: 32 samples x 128 channels, 16 (n,o) pairs per thread
    #pragma unroll 1
    for (int it = 0; it < 16; ++it) {
        const int pair = tid + it * 256;
        const int n = pair >> 7, o = pair & 127;
        const int4 rr = rois_s[n];
        const float b2o = b2s[o], s1o = s1s[o];
        const float z00 = zs[(4 * n + 0) * ZS_STRIDE + o];
        const float z01 = zs[(4 * n + 1) * ZS_STRIDE + o];
        const float z10 = zs[(4 * n + 2) * ZS_STRIDE + o];
        const float z11 = zs[(4 * n + 3) * ZS_STRIDE + o];

        int y0 = rr.x, x0 = rr.y;
        const int h = rr.z - rr.x, w = rr.w - rr.y;
        const bool inb = (rr.x >= 0 && rr.x < 11 && rr.y >= 0 && rr.y < 11 &&
                          rr.z >= 0 && rr.z < 11 && rr.w >= 0 && rr.w < 11);
        int cat;
        if      (inb && h == 4 && w == 4) cat = 0;
        else if (inb && h == 8 && w == 8) cat = 1;
        else if (inb && h == 4 && w == 8) cat = 2;
        else if (inb && h == 6 && w == 8) cat = 3;
        else { cat = 4; y0 = 1; x0 = 1; }

        auto feval = [&](int i, int j) -> float {
            float v = b2o;
            if ((i & 1) && (j & 1)) {
                v += s1o;
                const bool ia = (i == 3) || (i == 7);
                const bool ja = (j == 3) || (j == 7);
                if (ia && ja)
                    v += (i == 3) ? ((j == 3) ? z00 : z01)
                                  : ((j == 3) ? z10 : z11);
            }
            return v;
        };

        float cell[16];
        if (cat == 0) {
            for (int u = 0; u < 4; ++u)
                for (int v = 0; v < 4; ++v)
                    cell[u * 4 + v] = feval(y0 + u, x0 + v);
        } else if (cat == 1) {
            for (int u = 0; u < 4; ++u)
                for (int v = 0; v < 4; ++v) {
                    const int i0 = y0 + 2 * u, j0 = x0 + 2 * v;
                    cell[u * 4 + v] =
                        fmaxf(fmaxf(feval(i0, j0),     feval(i0, j0 + 1)),
                              fmaxf(feval(i0 + 1, j0), feval(i0 + 1, j0 + 1)));
                }
        } else if (cat == 2) {
            for (int u = 0; u < 4; ++u)
                for (int v = 0; v < 4; ++v) {
                    const int j0 = x0 + 2 * v;
                    cell[u * 4 + v] = fmaxf(feval(y0 + u, j0), feval(y0 + u, j0 + 1));
                }
        } else if (cat == 3) {
            for (int u = 0; u < 4; ++u)
                for (int v = 0; v < 4; ++v) {
                    const int j0 = x0 + 2 * v;
                    float m = -3.402823466e38f;
                    const int r0 = 2 * u - 1, r1 = 2 * u;
                    if (r0 >= 0) m = fmaxf(feval(y0 + r0, j0), feval(y0 + r0, j0 + 1));
                    if (r1 < 6)  m = fmaxf(m, fmaxf(feval(y0 + r1, j0),
                                                    feval(y0 + r1, j0 + 1)));
                    cell[u * 4 + v] = m;
                }
        } else {
            for (int u = 0; u < 4; ++u)
                for (int v = 0; v < 4; ++v) {
                    float m = -3.402823466e38f;
                    for (int di = 0; di < 3; ++di)
                        for (int dj = 0; dj < 3; ++dj)
                            m = fmaxf(m, feval(1 + 2 * u + di, 1 + 2 * v + dj));
                    cell[u * 4 + v] = m;
                }
        }

        __align__(16) float c16[16];
        #pragma unroll
        for (int i = 0; i < 16; ++i) c16[i] = to_tf32(cell[i]);
        float4* pp = (float4*)&g_P[(size_t)(n0 + n) * 2048 + o * 16];
        pp[0] = ((float4*)c16)[0]; pp[1] = ((float4*)c16)[1];
        pp[2] = ((float4*)c16)[2]; pp[3] = ((float4*)c16)[3];
    }
}

// ---------------------------------------------------------------------------
// Kernel 3: out = leakyrelu(P @ wl + bl), 1xTF32 mma.
// BM=128, BN=128, BK=64, K=2048, double-buffered (128KB smem).
// ---------------------------------------------------------------------------
#define NCHUNK3    32
#define GEMM_SMEM  (2u * STAGE_SZ)

__global__ __launch_bounds__(256, 1) void gemm3_kernel(const float* __restrict__ bias,
                                                       float* __restrict__ out) {
    extern __shared__ __align__(1024) char smem[];
    const uint32_t sb = (uint32_t)__cvta_generic_to_shared(smem);
    const int tid  = threadIdx.x;
    const int wid  = tid >> 5, lane = tid & 31;
    const int bn   = blockIdx.x * 128;
    const int bm   = blockIdx.y * 128;
    const int wm   = (wid >> 2) * 64;
    const int wn   = (wid & 3) * 32;

    float acc[4][4][4];
    #pragma unroll
    for (int i = 0; i < 4; ++i)
        #pragma unroll
        for (int j = 0; j < 4; ++j)
            #pragma unroll
            for (int q = 0; q < 4; ++q) acc[i][j][q] = 0.f;

    load_chunk_g(sb, g_P, g_WT, bm, bn, 2048, 2048, 0, tid);
    asm volatile("cp.async.commit_group;" ::: "memory");
    asm volatile("cp.async.wait_group 0;" ::: "memory");
    __syncthreads();

    for (int c = 0; c < NCHUNK3; ++c) {
        const uint32_t cur = sb + (uint32_t)(c & 1) * STAGE_SZ;
        const uint32_t nxt = sb + (uint32_t)((c & 1) ^ 1) * STAGE_SZ;
        if (c + 1 < NCHUNK3) {
            load_chunk_g(nxt, g_P, g_WT, bm, bn, 2048, 2048, (c + 1) * 64, tid);
            asm volatile("cp.async.commit_group;" ::: "memory");
        }
        mma_block(cur, acc, wm, wn, lane);
        if (c + 1 < NCHUNK3)
            asm volatile("cp.async.wait_group 0;" ::: "memory");
        __syncthreads();
    }

    const int er = lane >> 2, ec = (lane & 3) * 2;
    #pragma unroll
    for (int mt = 0; mt < 4; ++mt) {
        #pragma unroll
        for (int nt = 0; nt < 4; ++nt) {
            const int n = bn + wn + nt * 8 + ec;
            const float bv0 = bias[n], bv1 = bias[n + 1];
            #pragma unroll
            for (int half = 0; half < 2; ++half) {
                const int m = bm + wm + mt * 16 + er + half * 8;
                float h0 = acc[mt][nt][half * 2 + 0] + bv0;
                float h1 = acc[mt][nt][half * 2 + 1] + bv1;
                float2 o2;
                o2.x = h0 > 0.f ? h0 : 0.01f * h0;
                o2.y = h1 > 0.f ? h1 : 0.01f * h1;
                *(float2*)&out[(size_t)m * 1024 + n] = o2;
            }
        }
    }
}

// ---------------------------------------------------------------------------
extern "C" void kernel_launch(void* const* d_in, const int* in_sizes, int n_in,
                              void* d_out, int out_size) {
    const float* base = (const float*)d_in[0];
    const int*   rois = (const int*)d_in[1];
    const float* w1   = (const float*)d_in[2];
    const float* b1   = (const float*)d_in[3];
    const float* w2   = (const float*)d_in[4];
    const float* b2   = (const float*)d_in[5];
    const float* wl   = (const float*)d_in[6];
    const float* bl   = (const float*)d_in[7];
    float* out = (float*)d_out;

    cudaFuncSetAttribute(zgemm_kernel, cudaFuncAttributeMaxDynamicSharedMemorySize,
                         ZG_SMEM);
    cudaFuncSetAttribute(gemm3_kernel, cudaFuncAttributeMaxDynamicSharedMemorySize,
                         GEMM_SMEM);

    prep_kernel<<<65, 128>>>(w1, b1, w2);
    wsplit_kernel<<<dim3(32, 64), dim3(32, 8)>>>(wl);
    xsplit_kernel<<<NSAMP / 8, 256>>>(base);
    zgemm_kernel<<<NSAMP / 32, 256, ZG_SMEM>>>(rois, b2);
    gemm3_kernel<<<dim3(1024 / 128, NSAMP / 128), 256, GEMM_SMEM>>>(bl, out);
}

// round 6
// speedup vs baseline: 3.6933x; 1.0878x over previous
#include <cuda_runtime.h>
#include <cuda_bf16.h>
#include <math.h>
#include <stdint.h>

// ---------------------------------------------------------------------------
//   base_feat: (32,256,512,4,4) f32 -> 8192 samples of (512,16)
//   rois:(8192,4) i32  w1:(512,256) b1:(256) w2:(256,128) b2:(128)
//   wl:(2048,1024) bl:(1024)  out:(8192,1024) f32
//
// feat[o,i,j] = b2[o] + S1[o]*(i,j odd) + Z[o,a,b]*((i,j) in {3,7}^2)
// Z = X(32768x512) @ W^T(128x512) via 1xTF32 mma, pool fused in epilogue.
// out = leakyrelu(P(8192x2048) @ wl + bl) via 1xTF32 mma.
// Producers fused into one kernel; GEMMs use 3-stage cp.async pipelines.
// ---------------------------------------------------------------------------

#define NSAMP 8192

__device__ float g_S1[128];
__device__ float g_X[(size_t)NSAMP * 4 * 512];   // [m=4n+c][k] tf32
__device__ float g_WZ[128 * 512];                // W^T [o][k]  tf32
__device__ float g_P[(size_t)NSAMP * 2048];      // P   [n][o*16+cell] tf32
__device__ float g_WT[(size_t)1024 * 2048];      // wl^T [nn][k] tf32

#define SWZ128(off) ((off) ^ (((off) >> 3) & 0x70))

__device__ __forceinline__ float to_tf32(float x) {
    float r;
    asm("cvt.rna.tf32.f32 %0, %1;" : "=f"(r) : "f"(x));
    return r;
}
__device__ __forceinline__ void cp16(uint32_t dst, const void* src) {
    asm volatile("cp.async.cg.shared.global [%0], [%1], 16;"
                 :: "r"(dst), "l"(__cvta_generic_to_global(src)) : "memory");
}
__device__ __forceinline__ void ldm_x4(uint32_t addr, uint32_t& r0, uint32_t& r1,
                                       uint32_t& r2, uint32_t& r3) {
    asm volatile("ldmatrix.sync.aligned.m8n8.x4.shared.b16 {%0,%1,%2,%3}, [%4];"
                 : "=r"(r0), "=r"(r1), "=r"(r2), "=r"(r3) : "r"(addr));
}
__device__ __forceinline__ void mma_tf32(float& d0, float& d1, float& d2, float& d3,
                                         uint32_t a0, uint32_t a1, uint32_t a2,
                                         uint32_t a3, uint32_t b0, uint32_t b1) {
    asm volatile("mma.sync.aligned.m16n8k8.row.col.f32.tf32.tf32.f32 "
                 "{%0,%1,%2,%3}, {%4,%5,%6,%7}, {%8,%9}, {%0,%1,%2,%3};"
                 : "+f"(d0), "+f"(d1), "+f"(d2), "+f"(d3)
                 : "r"(a0), "r"(a1), "r"(a2), "r"(a3), "r"(b0), "r"(b1));
}

// shared GEMM building blocks (BK = 64 fp32, 3-stage pipeline) --------------
#define KSUB       16384u
#define B_OFF      32768u
#define STAGE_SZ   65536u
#define NSTAGE     3u

__device__ __forceinline__ void load_chunk_g(
    uint32_t sbase,
    const float* __restrict__ A, const float* __restrict__ B,
    int arow0, int brow0, size_t strideA, size_t strideB, int k0, int tid) {
    #pragma unroll
    for (int it = 0; it < 16; ++it) {
        const int g = tid + it * 256;            // 0..4095 (16B units)
        const int isB = g >> 11;
        const int e   = g & 2047;
        const int r   = e >> 4;                  // 0..127 rows
        const int u   = e & 15;                  // 16 x 16B per 64-fp32 row
        const uint32_t dst = sbase + (isB ? B_OFF : 0u) + (uint32_t)(u >> 3) * KSUB
                           + SWZ128((uint32_t)(r * 128 + (u & 7) * 16));
        const float* src = isB ? (B + (size_t)(brow0 + r) * strideB + k0 + u * 4)
                               : (A + (size_t)(arow0 + r) * strideA + k0 + u * 4);
        cp16(dst, src);
    }
}

__device__ __forceinline__ void mma_block(uint32_t cur, float acc[4][4][4],
                                          int wm, int wn, int lane) {
    const int r16  = lane & 15;
    const int h16  = (lane >> 4) * 16;   // 16B half selector
    #pragma unroll
    for (int ks = 0; ks < 8; ++ks) {
        const uint32_t abase = cur + (uint32_t)(ks >> 2) * KSUB;
        const uint32_t bbase = abase + B_OFF;
        const int kb = (ks & 3) * 32 + h16;
        uint32_t a[4][4], b[4][2];
        #pragma unroll
        for (int mt = 0; mt < 4; ++mt)
            ldm_x4(abase + SWZ128((uint32_t)((wm + mt * 16 + r16) * 128 + kb)),
                   a[mt][0], a[mt][1], a[mt][2], a[mt][3]);
        #pragma unroll
        for (int q = 0; q < 2; ++q) {
            uint32_t r0, r1, r2, r3;
            ldm_x4(bbase + SWZ128((uint32_t)((wn + q * 16 + r16) * 128 + kb)),
                   r0, r1, r2, r3);
            b[2 * q][0] = r0;     b[2 * q][1] = r2;
            b[2 * q + 1][0] = r1; b[2 * q + 1][1] = r3;
        }
        #pragma unroll
        for (int mt = 0; mt < 4; ++mt)
            #pragma unroll
            for (int nt = 0; nt < 4; ++nt)
                mma_tf32(acc[mt][nt][0], acc[mt][nt][1],
                         acc[mt][nt][2], acc[mt][nt][3],
                         a[mt][0], a[mt][1], a[mt][2], a[mt][3],
                         b[nt][0], b[nt][1]);
    }
}

// ---------------------------------------------------------------------------
// Kernel 1 (fused producers), 256 threads, grid partitioned by blockIdx.x:
//   [0,256):     W = w1 @ w2 -> tf32 g_WZ [o][k]   (2 k-rows per block)
//   [256]:       S1 = b1 @ w2 (f32)
//   [257,2305):  transpose wl -> g_WT [nn][k] tf32 (32x32 tiles)
//   [2305,3329): extract centers of base_feat -> tf32 g_X [m][k]
// ---------------------------------------------------------------------------
#define PREP_B0   0
#define S1_B      256
#define WSP_B0    257
#define XSP_B0    2305
#define PREP_GRID 3329

__global__ __launch_bounds__(256) void prep_all(const float* __restrict__ w1,
                                                const float* __restrict__ b1,
                                                const float* __restrict__ w2,
                                                const float* __restrict__ wl,
                                                const float* __restrict__ base) {
    __shared__ float w1s[2][256];
    __shared__ float t[32][33];
    const int b   = blockIdx.x;
    const int tid = threadIdx.x;

    if (b < S1_B) {
        // --- W = w1 @ w2: block handles k-rows 2b, 2b+1 ---
        for (int i = tid; i < 512; i += 256)
            ((float*)w1s)[i] = w1[(size_t)b * 512 + i];
        __syncthreads();
        const int kk = tid >> 7, o = tid & 127;
        float acc = 0.f;
        #pragma unroll 4
        for (int c = 0; c < 256; ++c)
            acc = fmaf(w1s[kk][c], w2[c * 128 + o], acc);
        g_WZ[o * 512 + b * 2 + kk] = to_tf32(acc);
    } else if (b == S1_B) {
        if (tid < 128) {
            float acc = 0.f;
            for (int c = 0; c < 256; ++c) acc = fmaf(b1[c], w2[c * 128 + tid], acc);
            g_S1[tid] = acc;
        }
    } else if (b < XSP_B0) {
        // --- transpose wl tile ---
        const int w  = b - WSP_B0;
        const int n0 = (w & 31) * 32, k0 = (w >> 5) * 32;
        const int tx = tid & 31, ty = tid >> 5;   // 32 x 8
        #pragma unroll
        for (int j = 0; j < 4; ++j)
            t[ty + j * 8][tx] = wl[(size_t)(k0 + ty + j * 8) * 1024 + n0 + tx];
        __syncthreads();
        #pragma unroll
        for (int j = 0; j < 4; ++j)
            g_WT[(size_t)(n0 + ty + j * 8) * 2048 + k0 + tx] =
                to_tf32(t[tx][ty + j * 8]);
    } else {
        // --- extract 2x2 centers ---
        const int n0 = (b - XSP_B0) * 8;
        for (int s = 0; s < 8; ++s) {
            const int n = n0 + s;
            const float4* src = (const float4*)(base + (size_t)n * 8192);
            #pragma unroll
            for (int i = 0; i < 2; ++i) {
                const int k = tid + i * 256;
                const float4 v1 = src[k * 4 + 1];   // f5,f6 = centers 0,1
                const float4 v2 = src[k * 4 + 2];   // f9,f10 = centers 2,3
                const size_t m0 = (size_t)(4 * n) * 512 + k;
                g_X[m0 + 0 * 512] = to_tf32(v1.y);
                g_X[m0 + 1 * 512] = to_tf32(v1.z);
                g_X[m0 + 2 * 512] = to_tf32(v2.y);
                g_X[m0 + 3 * 512] = to_tf32(v2.z);
            }
        }
    }
}

// ---------------------------------------------------------------------------
// Kernel 2: zgemm (Z = X @ W^T) with fused categorized max-pool epilogue.
// BM=128 (32 samples), BN=128, K=512, BK=64, 3-stage pipeline.
// ---------------------------------------------------------------------------
#define ZCHUNK    8
#define ZS_STRIDE 136
#define SM_ROIS   (NSTAGE * STAGE_SZ)
#define SM_B2     (SM_ROIS + 512u)
#define SM_S1     (SM_B2 + 512u)
#define ZG_SMEM   (SM_S1 + 512u)

__global__ __launch_bounds__(256, 1) void zgemm_kernel(const int* __restrict__ rois,
                                                       const float* __restrict__ b2) {
    extern __shared__ __align__(1024) char smem[];
    const uint32_t sb = (uint32_t)__cvta_generic_to_shared(smem);
    const int tid  = threadIdx.x;
    const int wid  = tid >> 5, lane = tid & 31;
    const int n0   = blockIdx.x * 32;
    const int bm   = blockIdx.x * 128;
    const int wm   = (wid >> 2) * 64;
    const int wn   = (wid & 3) * 32;

    int4*  rois_s = (int4*)(smem + SM_ROIS);
    float* b2s    = (float*)(smem + SM_B2);
    float* s1s    = (float*)(smem + SM_S1);
    if (tid < 32) rois_s[tid] = ((const int4*)rois)[n0 + tid];
    if (tid >= 128) { b2s[tid - 128] = b2[tid - 128]; s1s[tid - 128] = g_S1[tid - 128]; }

    float acc[4][4][4];
    #pragma unroll
    for (int i = 0; i < 4; ++i)
        #pragma unroll
        for (int j = 0; j < 4; ++j)
            #pragma unroll
            for (int q = 0; q < 4; ++q) acc[i][j][q] = 0.f;

    load_chunk_g(sb, g_X, g_WZ, bm, 0, 512, 512, 0, tid);
    asm volatile("cp.async.commit_group;" ::: "memory");
    load_chunk_g(sb + STAGE_SZ, g_X, g_WZ, bm, 0, 512, 512, 64, tid);
    asm volatile("cp.async.commit_group;" ::: "memory");

    for (int c = 0; c < ZCHUNK; ++c) {
        if (c + 1 < ZCHUNK)
            asm volatile("cp.async.wait_group 1;" ::: "memory");
        else
            asm volatile("cp.async.wait_group 0;" ::: "memory");
        __syncthreads();
        if (c + 2 < ZCHUNK) {
            load_chunk_g(sb + (uint32_t)((c + 2) % 3) * STAGE_SZ,
                         g_X, g_WZ, bm, 0, 512, 512, (c + 2) * 64, tid);
            asm volatile("cp.async.commit_group;" ::: "memory");
        }
        mma_block(sb + (uint32_t)(c % 3) * STAGE_SZ, acc, wm, wn, lane);
    }
    __syncthreads();

    // stage Z tile to smem (f32, padded stride)
    float* zs = (float*)smem;
    const int er = lane >> 2, ec = (lane & 3) * 2;
    #pragma unroll
    for (int mt = 0; mt < 4; ++mt)
        #pragma unroll
        for (int nt = 0; nt < 4; ++nt)
            #pragma unroll
            for (int half = 0; half < 2; ++half) {
                const int row = wm + mt * 16 + er + half * 8;
                const int col = wn + nt * 8 + ec;
                *(float2*)&zs[row * ZS_STRIDE + col] =
                    make_float2(acc[mt][nt][half * 2 + 0], acc[mt][nt][half * 2 + 1]);
            }
    __syncthreads();

    // fused pool: 32 samples x 128 channels, 16 (n,o) pairs per thread
    #pragma unroll 1
    for (int it = 0; it < 16; ++it) {
        const int pair = tid + it * 256;
        const int n = pair >> 7, o = pair & 127;
        const int4 rr = rois_s[n];
        const float b2o = b2s[o], s1o = s1s[o];
        const float z00 = zs[(4 * n + 0) * ZS_STRIDE + o];
        const float z01 = zs[(4 * n + 1) * ZS_STRIDE + o];
        const float z10 = zs[(4 * n + 2) * ZS_STRIDE + o];
        const float z11 = zs[(4 * n + 3) * ZS_STRIDE + o];

        int y0 = rr.x, x0 = rr.y;
        const int h = rr.z - rr.x, w = rr.w - rr.y;
        const bool inb = (rr.x >= 0 && rr.x < 11 && rr.y >= 0 && rr.y < 11 &&
                          rr.z >= 0 && rr.z < 11 && rr.w >= 0 && rr.w < 11);
        int cat;
        if      (inb && h == 4 && w == 4) cat = 0;
        else if (inb && h == 8 && w == 8) cat = 1;
        else if (inb && h == 4 && w == 8) cat = 2;
        else if (inb && h == 6 && w == 8) cat = 3;
        else { cat = 4; y0 = 1; x0 = 1; }

        auto feval = [&](int i, int j) -> float {
            float v = b2o;
            if ((i & 1) && (j & 1)) {
                v += s1o;
                const bool ia = (i == 3) || (i == 7);
                const bool ja = (j == 3) || (j == 7);
                if (ia && ja)
                    v += (i == 3) ? ((j == 3) ? z00 : z01)
                                  : ((j == 3) ? z10 : z11);
            }
            return v;
        };

        float cell[16];
        if (cat == 0) {
            for (int u = 0; u < 4; ++u)
                for (int v = 0; v < 4; ++v)
                    cell[u * 4 + v] = feval(y0 + u, x0 + v);
        } else if (cat == 1) {
            for (int u = 0; u < 4; ++u)
                for (int v = 0; v < 4; ++v) {
                    const int i0 = y0 + 2 * u, j0 = x0 + 2 * v;
                    cell[u * 4 + v] =
                        fmaxf(fmaxf(feval(i0, j0),     feval(i0, j0 + 1)),
                              fmaxf(feval(i0 + 1, j0), feval(i0 + 1, j0 + 1)));
                }
        } else if (cat == 2) {
            for (int u = 0; u < 4; ++u)
                for (int v = 0; v < 4; ++v) {
                    const int j0 = x0 + 2 * v;
                    cell[u * 4 + v] = fmaxf(feval(y0 + u, j0), feval(y0 + u, j0 + 1));
                }
        } else if (cat == 3) {
            for (int u = 0; u < 4; ++u)
                for (int v = 0; v < 4; ++v) {
                    const int j0 = x0 + 2 * v;
                    float m = -3.402823466e38f;
                    const int r0 = 2 * u - 1, r1 = 2 * u;
                    if (r0 >= 0) m = fmaxf(feval(y0 + r0, j0), feval(y0 + r0, j0 + 1));
                    if (r1 < 6)  m = fmaxf(m, fmaxf(feval(y0 + r1, j0),
                                                    feval(y0 + r1, j0 + 1)));
                    cell[u * 4 + v] = m;
                }
        } else {
            for (int u = 0; u < 4; ++u)
                for (int v = 0; v < 4; ++v) {
                    float m = -3.402823466e38f;
                    for (int di = 0; di < 3; ++di)
                        for (int dj = 0; dj < 3; ++dj)
                            m = fmaxf(m, feval(1 + 2 * u + di, 1 + 2 * v + dj));
                    cell[u * 4 + v] = m;
                }
        }

        __align__(16) float c16[16];
        #pragma unroll
        for (int i = 0; i < 16; ++i) c16[i] = to_tf32(cell[i]);
        float4* pp = (float4*)&g_P[(size_t)(n0 + n) * 2048 + o * 16];
        pp[0] = ((float4*)c16)[0]; pp[1] = ((float4*)c16)[1];
        pp[2] = ((float4*)c16)[2]; pp[3] = ((float4*)c16)[3];
    }
}

// ---------------------------------------------------------------------------
// Kernel 3: out = leakyrelu(P @ wl + bl), 1xTF32 mma.
// BM=128, BN=128, BK=64, K=2048, 3-stage pipeline (192KB smem).
// ---------------------------------------------------------------------------
#define NCHUNK3    32
#define GEMM_SMEM  (NSTAGE * STAGE_SZ)

__global__ __launch_bounds__(256, 1) void gemm3_kernel(const float* __restrict__ bias,
                                                       float* __restrict__ out) {
    extern __shared__ __align__(1024) char smem[];
    const uint32_t sb = (uint32_t)__cvta_generic_to_shared(smem);
    const int tid  = threadIdx.x;
    const int wid  = tid >> 5, lane = tid & 31;
    const int bn   = blockIdx.x * 128;
    const int bm   = blockIdx.y * 128;
    const int wm   = (wid >> 2) * 64;
    const int wn   = (wid & 3) * 32;

    float acc[4][4][4];
    #pragma unroll
    for (int i = 0; i < 4; ++i)
        #pragma unroll
        for (int j = 0; j < 4; ++j)
            #pragma unroll
            for (int q = 0; q < 4; ++q) acc[i][j][q] = 0.f;

    load_chunk_g(sb, g_P, g_WT, bm, bn, 2048, 2048, 0, tid);
    asm volatile("cp.async.commit_group;" ::: "memory");
    load_chunk_g(sb + STAGE_SZ, g_P, g_WT, bm, bn, 2048, 2048, 64, tid);
    asm volatile("cp.async.commit_group;" ::: "memory");

    for (int c = 0; c < NCHUNK3; ++c) {
        if (c + 1 < NCHUNK3)
            asm volatile("cp.async.wait_group 1;" ::: "memory");
        else
            asm volatile("cp.async.wait_group 0;" ::: "memory");
        __syncthreads();
        if (c + 2 < NCHUNK3) {
            load_chunk_g(sb + (uint32_t)((c + 2) % 3) * STAGE_SZ,
                         g_P, g_WT, bm, bn, 2048, 2048, (c + 2) * 64, tid);
            asm volatile("cp.async.commit_group;" ::: "memory");
        }
        mma_block(sb + (uint32_t)(c % 3) * STAGE_SZ, acc, wm, wn, lane);
    }

    const int er = lane >> 2, ec = (lane & 3) * 2;
    #pragma unroll
    for (int mt = 0; mt < 4; ++mt) {
        #pragma unroll
        for (int nt = 0; nt < 4; ++nt) {
            const int n = bn + wn + nt * 8 + ec;
            const float bv0 = bias[n], bv1 = bias[n + 1];
            #pragma unroll
            for (int half = 0; half < 2; ++half) {
                const int m = bm + wm + mt * 16 + er + half * 8;
                float h0 = acc[mt][nt][half * 2 + 0] + bv0;
                float h1 = acc[mt][nt][half * 2 + 1] + bv1;
                float2 o2;
                o2.x = h0 > 0.f ? h0 : 0.01f * h0;
                o2.y = h1 > 0.f ? h1 : 0.01f * h1;
                *(float2*)&out[(size_t)m * 1024 + n] = o2;
            }
        }
    }
}

// ---------------------------------------------------------------------------
extern "C" void kernel_launch(void* const* d_in, const int* in_sizes, int n_in,
                              void* d_out, int out_size) {
    const float* base = (const float*)d_in[0];
    const int*   rois = (const int*)d_in[1];
    const float* w1   = (const float*)d_in[2];
    const float* b1   = (const float*)d_in[3];
    const float* w2   = (const float*)d_in[4];
    const float* b2   = (const float*)d_in[5];
    const float* wl   = (const float*)d_in[6];
    const float* bl   = (const float*)d_in[7];
    float* out = (float*)d_out;

    cudaFuncSetAttribute(zgemm_kernel, cudaFuncAttributeMaxDynamicSharedMemorySize,
                         ZG_SMEM);
    cudaFuncSetAttribute(gemm3_kernel, cudaFuncAttributeMaxDynamicSharedMemorySize,
                         GEMM_SMEM);

    prep_all<<<PREP_GRID, 256>>>(w1, b1, w2, wl, base);
    zgemm_kernel<<<NSAMP / 32, 256, ZG_SMEM>>>(rois, b2);
    gemm3_kernel<<<dim3(1024 / 128, NSAMP / 128), 256, GEMM_SMEM>>>(bl, out);
}

// round 7
// speedup vs baseline: 3.9549x; 1.0708x over previous
#include <cuda_runtime.h>
#include <cuda_bf16.h>
#include <math.h>
#include <stdint.h>

// ---------------------------------------------------------------------------
//   base_feat: (32,256,512,4,4) f32 -> 8192 samples of (512,16)
//   rois:(8192,4) i32  w1:(512,256) b1:(256) w2:(256,128) b2:(128)
//   wl:(2048,1024) bl:(1024)  out:(8192,1024) f32
//
// feat[o,i,j] = b2[o] + S1[o]*(i,j odd) + Z[o,a,b]*((i,j) in {3,7}^2)
// Z = X(32768x512) @ W^T(128x512) via 1xTF32 mma, pool fused in epilogue.
// out = leakyrelu(P(8192x2048) @ wl + bl) via 1xTF32 mma,
//   BM=256/BN=128/BK=32, 4-stage cp.async pipeline (L2-traffic-optimized).
// ---------------------------------------------------------------------------

#define NSAMP 8192

__device__ float g_S1[128];
__device__ float g_X[(size_t)NSAMP * 4 * 512];   // [m=4n+c][k] tf32
__device__ float g_WZ[128 * 512];                // W^T [o][k]  tf32
__device__ float g_P[(size_t)NSAMP * 2048];      // P   [n][o*16+cell] tf32
__device__ float g_WT[(size_t)1024 * 2048];      // wl^T [nn][k] tf32

#define SWZ128(off) ((off) ^ (((off) >> 3) & 0x70))

__device__ __forceinline__ float to_tf32(float x) {
    float r;
    asm("cvt.rna.tf32.f32 %0, %1;" : "=f"(r) : "f"(x));
    return r;
}
__device__ __forceinline__ void cp16(uint32_t dst, const void* src) {
    asm volatile("cp.async.cg.shared.global [%0], [%1], 16;"
                 :: "r"(dst), "l"(__cvta_generic_to_global(src)) : "memory");
}
__device__ __forceinline__ void ldm_x4(uint32_t addr, uint32_t& r0, uint32_t& r1,
                                       uint32_t& r2, uint32_t& r3) {
    asm volatile("ldmatrix.sync.aligned.m8n8.x4.shared.b16 {%0,%1,%2,%3}, [%4];"
                 : "=r"(r0), "=r"(r1), "=r"(r2), "=r"(r3) : "r"(addr));
}
__device__ __forceinline__ void mma_tf32(float& d0, float& d1, float& d2, float& d3,
                                         uint32_t a0, uint32_t a1, uint32_t a2,
                                         uint32_t a3, uint32_t b0, uint32_t b1) {
    asm volatile("mma.sync.aligned.m16n8k8.row.col.f32.tf32.tf32.f32 "
                 "{%0,%1,%2,%3}, {%4,%5,%6,%7}, {%8,%9}, {%0,%1,%2,%3};"
                 : "+f"(d0), "+f"(d1), "+f"(d2), "+f"(d3)
                 : "r"(a0), "r"(a1), "r"(a2), "r"(a3), "r"(b0), "r"(b1));
}

// ===== zgemm building blocks (BK = 64 fp32, 3-stage) =======================
#define KSUB       16384u
#define B_OFF      32768u
#define STAGE_SZ   65536u
#define NSTAGE     3u

__device__ __forceinline__ void load_chunk_g(
    uint32_t sbase,
    const float* __restrict__ A, const float* __restrict__ B,
    int arow0, int brow0, size_t strideA, size_t strideB, int k0, int tid) {
    #pragma unroll
    for (int it = 0; it < 16; ++it) {
        const int g = tid + it * 256;            // 0..4095 (16B units)
        const int isB = g >> 11;
        const int e   = g & 2047;
        const int r   = e >> 4;
        const int u   = e & 15;
        const uint32_t dst = sbase + (isB ? B_OFF : 0u) + (uint32_t)(u >> 3) * KSUB
                           + SWZ128((uint32_t)(r * 128 + (u & 7) * 16));
        const float* src = isB ? (B + (size_t)(brow0 + r) * strideB + k0 + u * 4)
                               : (A + (size_t)(arow0 + r) * strideA + k0 + u * 4);
        cp16(dst, src);
    }
}

__device__ __forceinline__ void mma_block(uint32_t cur, float acc[4][4][4],
                                          int wm, int wn, int lane) {
    const int r16  = lane & 15;
    const int h16  = (lane >> 4) * 16;
    #pragma unroll
    for (int ks = 0; ks < 8; ++ks) {
        const uint32_t abase = cur + (uint32_t)(ks >> 2) * KSUB;
        const uint32_t bbase = abase + B_OFF;
        const int kb = (ks & 3) * 32 + h16;
        uint32_t a[4][4], b[4][2];
        #pragma unroll
        for (int mt = 0; mt < 4; ++mt)
            ldm_x4(abase + SWZ128((uint32_t)((wm + mt * 16 + r16) * 128 + kb)),
                   a[mt][0], a[mt][1], a[mt][2], a[mt][3]);
        #pragma unroll
        for (int q = 0; q < 2; ++q) {
            uint32_t r0, r1, r2, r3;
            ldm_x4(bbase + SWZ128((uint32_t)((wn + q * 16 + r16) * 128 + kb)),
                   r0, r1, r2, r3);
            b[2 * q][0] = r0;     b[2 * q][1] = r2;
            b[2 * q + 1][0] = r1; b[2 * q + 1][1] = r3;
        }
        #pragma unroll
        for (int mt = 0; mt < 4; ++mt)
            #pragma unroll
            for (int nt = 0; nt < 4; ++nt)
                mma_tf32(acc[mt][nt][0], acc[mt][nt][1],
                         acc[mt][nt][2], acc[mt][nt][3],
                         a[mt][0], a[mt][1], a[mt][2], a[mt][3],
                         b[nt][0], b[nt][1]);
    }
}

// ---------------------------------------------------------------------------
// Kernel 1 (fused producers), 256 threads, grid partitioned by blockIdx.x
// ---------------------------------------------------------------------------
#define S1_B      256
#define WSP_B0    257
#define XSP_B0    2305
#define PREP_GRID 3329

__global__ __launch_bounds__(256) void prep_all(const float* __restrict__ w1,
                                                const float* __restrict__ b1,
                                                const float* __restrict__ w2,
                                                const float* __restrict__ wl,
                                                const float* __restrict__ base) {
    __shared__ float w1s[2][256];
    __shared__ float t[32][33];
    const int b   = blockIdx.x;
    const int tid = threadIdx.x;

    if (b < S1_B) {
        for (int i = tid; i < 512; i += 256)
            ((float*)w1s)[i] = w1[(size_t)b * 512 + i];
        __syncthreads();
        const int kk = tid >> 7, o = tid & 127;
        float acc = 0.f;
        #pragma unroll 4
        for (int c = 0; c < 256; ++c)
            acc = fmaf(w1s[kk][c], w2[c * 128 + o], acc);
        g_WZ[o * 512 + b * 2 + kk] = to_tf32(acc);
    } else if (b == S1_B) {
        if (tid < 128) {
            float acc = 0.f;
            for (int c = 0; c < 256; ++c) acc = fmaf(b1[c], w2[c * 128 + tid], acc);
            g_S1[tid] = acc;
        }
    } else if (b < XSP_B0) {
        const int w  = b - WSP_B0;
        const int n0 = (w & 31) * 32, k0 = (w >> 5) * 32;
        const int tx = tid & 31, ty = tid >> 5;   // 32 x 8
        #pragma unroll
        for (int j = 0; j < 4; ++j)
            t[ty + j * 8][tx] = wl[(size_t)(k0 + ty + j * 8) * 1024 + n0 + tx];
        __syncthreads();
        #pragma unroll
        for (int j = 0; j < 4; ++j)
            g_WT[(size_t)(n0 + ty + j * 8) * 2048 + k0 + tx] =
                to_tf32(t[tx][ty + j * 8]);
    } else {
        // --- extract 2x2 centers (streaming loads: don't pollute L2) ---
        const int n0 = (b - XSP_B0) * 8;
        for (int s = 0; s < 8; ++s) {
            const int n = n0 + s;
            const float4* src = (const float4*)(base + (size_t)n * 8192);
            #pragma unroll
            for (int i = 0; i < 2; ++i) {
                const int k = tid + i * 256;
                const float4 v1 = __ldcs(&src[k * 4 + 1]);   // f5,f6
                const float4 v2 = __ldcs(&src[k * 4 + 2]);   // f9,f10
                const size_t m0 = (size_t)(4 * n) * 512 + k;
                g_X[m0 + 0 * 512] = to_tf32(v1.y);
                g_X[m0 + 1 * 512] = to_tf32(v1.z);
                g_X[m0 + 2 * 512] = to_tf32(v2.y);
                g_X[m0 + 3 * 512] = to_tf32(v2.z);
            }
        }
    }
}

// ---------------------------------------------------------------------------
// Kernel 2: zgemm (Z = X @ W^T) with fused categorized max-pool epilogue.
// BM=128 (32 samples), BN=128, K=512, BK=64, 3-stage pipeline.
// ---------------------------------------------------------------------------
#define ZCHUNK    8
#define ZS_STRIDE 136
#define SM_ROIS   (NSTAGE * STAGE_SZ)
#define SM_B2     (SM_ROIS + 512u)
#define SM_S1     (SM_B2 + 512u)
#define ZG_SMEM   (SM_S1 + 512u)

__global__ __launch_bounds__(256, 1) void zgemm_kernel(const int* __restrict__ rois,
                                                       const float* __restrict__ b2) {
    extern __shared__ __align__(1024) char smem[];
    const uint32_t sb = (uint32_t)__cvta_generic_to_shared(smem);
    const int tid  = threadIdx.x;
    const int wid  = tid >> 5, lane = tid & 31;
    const int n0   = blockIdx.x * 32;
    const int bm   = blockIdx.x * 128;
    const int wm   = (wid >> 2) * 64;
    const int wn   = (wid & 3) * 32;

    int4*  rois_s = (int4*)(smem + SM_ROIS);
    float* b2s    = (float*)(smem + SM_B2);
    float* s1s    = (float*)(smem + SM_S1);
    if (tid < 32) rois_s[tid] = ((const int4*)rois)[n0 + tid];
    if (tid >= 128) { b2s[tid - 128] = b2[tid - 128]; s1s[tid - 128] = g_S1[tid - 128]; }

    float acc[4][4][4];
    #pragma unroll
    for (int i = 0; i < 4; ++i)
        #pragma unroll
        for (int j = 0; j < 4; ++j)
            #pragma unroll
            for (int q = 0; q < 4; ++q) acc[i][j][q] = 0.f;

    load_chunk_g(sb, g_X, g_WZ, bm, 0, 512, 512, 0, tid);
    asm volatile("cp.async.commit_group;" ::: "memory");
    load_chunk_g(sb + STAGE_SZ, g_X, g_WZ, bm, 0, 512, 512, 64, tid);
    asm volatile("cp.async.commit_group;" ::: "memory");

    for (int c = 0; c < ZCHUNK; ++c) {
        if (c + 1 < ZCHUNK)
            asm volatile("cp.async.wait_group 1;" ::: "memory");
        else
            asm volatile("cp.async.wait_group 0;" ::: "memory");
        __syncthreads();
        if (c + 2 < ZCHUNK) {
            load_chunk_g(sb + (uint32_t)((c + 2) % 3) * STAGE_SZ,
                         g_X, g_WZ, bm, 0, 512, 512, (c + 2) * 64, tid);
            asm volatile("cp.async.commit_group;" ::: "memory");
        }
        mma_block(sb + (uint32_t)(c % 3) * STAGE_SZ, acc, wm, wn, lane);
    }
    __syncthreads();

    float* zs = (float*)smem;
    const int er = lane >> 2, ec = (lane & 3) * 2;
    #pragma unroll
    for (int mt = 0; mt < 4; ++mt)
        #pragma unroll
        for (int nt = 0; nt < 4; ++nt)
            #pragma unroll
            for (int half = 0; half < 2; ++half) {
                const int row = wm + mt * 16 + er + half * 8;
                const int col = wn + nt * 8 + ec;
                *(float2*)&zs[row * ZS_STRIDE + col] =
                    make_float2(acc[mt][nt][half * 2 + 0], acc[mt][nt][half * 2 + 1]);
            }
    __syncthreads();

    #pragma unroll 1
    for (int it = 0; it < 16; ++it) {
        const int pair = tid + it * 256;
        const int n = pair >> 7, o = pair & 127;
        const int4 rr = rois_s[n];
        const float b2o = b2s[o], s1o = s1s[o];
        const float z00 = zs[(4 * n + 0) * ZS_STRIDE + o];
        const float z01 = zs[(4 * n + 1) * ZS_STRIDE + o];
        const float z10 = zs[(4 * n + 2) * ZS_STRIDE + o];
        const float z11 = zs[(4 * n + 3) * ZS_STRIDE + o];

        int y0 = rr.x, x0 = rr.y;
        const int h = rr.z - rr.x, w = rr.w - rr.y;
        const bool inb = (rr.x >= 0 && rr.x < 11 && rr.y >= 0 && rr.y < 11 &&
                          rr.z >= 0 && rr.z < 11 && rr.w >= 0 && rr.w < 11);
        int cat;
        if      (inb && h == 4 && w == 4) cat = 0;
        else if (inb && h == 8 && w == 8) cat = 1;
        else if (inb && h == 4 && w == 8) cat = 2;
        else if (inb && h == 6 && w == 8) cat = 3;
        else { cat = 4; y0 = 1; x0 = 1; }

        auto feval = [&](int i, int j) -> float {
            float v = b2o;
            if ((i & 1) && (j & 1)) {
                v += s1o;
                const bool ia = (i == 3) || (i == 7);
                const bool ja = (j == 3) || (j == 7);
                if (ia && ja)
                    v += (i == 3) ? ((j == 3) ? z00 : z01)
                                  : ((j == 3) ? z10 : z11);
            }
            return v;
        };

        float cell[16];
        if (cat == 0) {
            for (int u = 0; u < 4; ++u)
                for (int v = 0; v < 4; ++v)
                    cell[u * 4 + v] = feval(y0 + u, x0 + v);
        } else if (cat == 1) {
            for (int u = 0; u < 4; ++u)
                for (int v = 0; v < 4; ++v) {
                    const int i0 = y0 + 2 * u, j0 = x0 + 2 * v;
                    cell[u * 4 + v] =
                        fmaxf(fmaxf(feval(i0, j0),     feval(i0, j0 + 1)),
                              fmaxf(feval(i0 + 1, j0), feval(i0 + 1, j0 + 1)));
                }
        } else if (cat == 2) {
            for (int u = 0; u < 4; ++u)
                for (int v = 0; v < 4; ++v) {
                    const int j0 = x0 + 2 * v;
                    cell[u * 4 + v] = fmaxf(feval(y0 + u, j0), feval(y0 + u, j0 + 1));
                }
        } else if (cat == 3) {
            for (int u = 0; u < 4; ++u)
                for (int v = 0; v < 4; ++v) {
                    const int j0 = x0 + 2 * v;
                    float m = -3.402823466e38f;
                    const int r0 = 2 * u - 1, r1 = 2 * u;
                    if (r0 >= 0) m = fmaxf(feval(y0 + r0, j0), feval(y0 + r0, j0 + 1));
                    if (r1 < 6)  m = fmaxf(m, fmaxf(feval(y0 + r1, j0),
                                                    feval(y0 + r1, j0 + 1)));
                    cell[u * 4 + v] = m;
                }
        } else {
            for (int u = 0; u < 4; ++u)
                for (int v = 0; v < 4; ++v) {
                    float m = -3.402823466e38f;
                    for (int di = 0; di < 3; ++di)
                        for (int dj = 0; dj < 3; ++dj)
                            m = fmaxf(m, feval(1 + 2 * u + di, 1 + 2 * v + dj));
                    cell[u * 4 + v] = m;
                }
        }

        __align__(16) float c16[16];
        #pragma unroll
        for (int i = 0; i < 16; ++i) c16[i] = to_tf32(cell[i]);
        float4* pp = (float4*)&g_P[(size_t)(n0 + n) * 2048 + o * 16];
        pp[0] = ((float4*)c16)[0]; pp[1] = ((float4*)c16)[1];
        pp[2] = ((float4*)c16)[2]; pp[3] = ((float4*)c16)[3];
    }
}

// ---------------------------------------------------------------------------
// Kernel 3: out = leakyrelu(P @ wl + bl), 1xTF32 mma.
// BM=256, BN=128, BK=32, K=2048, 4-stage pipeline (192KB smem).
// 8 warps in 4(m) x 2(n) grid, warp tile 64x64.
// ---------------------------------------------------------------------------
#define NCHUNK3    64
#define ST3       49152u    // A 32KB + B 16KB
#define B3_OFF    32768u
#define GEMM_SMEM (4u * ST3)

__device__ __forceinline__ void load_chunk3(uint32_t sbase, int bm, int bn,
                                            int k0, int tid) {
    #pragma unroll
    for (int it = 0; it < 12; ++it) {
        const int g = tid + it * 256;            // 0..3071 (16B units)
        if (g < 2048) {                          // A: 256 rows x 128B
            const int r = g >> 3, u = g & 7;
            cp16(sbase + SWZ128((uint32_t)(r * 128 + u * 16)),
                 &g_P[(size_t)(bm + r) * 2048 + k0 + u * 4]);
        } else {                                 // B: 128 rows x 128B
            const int e = g - 2048;
            const int r = e >> 3, u = e & 7;
            cp16(sbase + B3_OFF + SWZ128((uint32_t)(r * 128 + u * 16)),
                 &g_WT[(size_t)(bn + r) * 2048 + k0 + u * 4]);
        }
    }
}

__global__ __launch_bounds__(256, 1) void gemm3_kernel(const float* __restrict__ bias,
                                                       float* __restrict__ out) {
    extern __shared__ __align__(1024) char smem[];
    const uint32_t sb = (uint32_t)__cvta_generic_to_shared(smem);
    const int tid  = threadIdx.x;
    const int wid  = tid >> 5, lane = tid & 31;
    const int bn   = blockIdx.x * 128;
    const int bm   = blockIdx.y * 256;
    const int wm   = (wid >> 1) * 64;   // 4 m-warps
    const int wn   = (wid & 1) * 64;    // 2 n-warps

    float acc[4][8][4];
    #pragma unroll
    for (int i = 0; i < 4; ++i)
        #pragma unroll
        for (int j = 0; j < 8; ++j)
            #pragma unroll
            for (int q = 0; q < 4; ++q) acc[i][j][q] = 0.f;

    load_chunk3(sb, bm, bn, 0, tid);
    asm volatile("cp.async.commit_group;" ::: "memory");
    load_chunk3(sb + ST3, bm, bn, 32, tid);
    asm volatile("cp.async.commit_group;" ::: "memory");
    load_chunk3(sb + 2u * ST3, bm, bn, 64, tid);
    asm volatile("cp.async.commit_group;" ::: "memory");

    const int r16 = lane & 15;
    const int h16 = (lane >> 4) * 16;

    for (int c = 0; c < NCHUNK3; ++c) {
        if (c + 2 < NCHUNK3)
            asm volatile("cp.async.wait_group 2;" ::: "memory");
        else if (c + 1 < NCHUNK3)
            asm volatile("cp.async.wait_group 1;" ::: "memory");
        else
            asm volatile("cp.async.wait_group 0;" ::: "memory");
        __syncthreads();
        if (c + 3 < NCHUNK3) {
            load_chunk3(sb + (uint32_t)((c + 3) & 3) * ST3, bm, bn,
                        (c + 3) * 32, tid);
            asm volatile("cp.async.commit_group;" ::: "memory");
        }

        const uint32_t cur = sb + (uint32_t)(c & 3) * ST3;
        #pragma unroll
        for (int ks = 0; ks < 4; ++ks) {
            const int kb = ks * 32 + h16;
            uint32_t a[4][4], b[8][2];
            #pragma unroll
            for (int mt = 0; mt < 4; ++mt)
                ldm_x4(cur + SWZ128((uint32_t)((wm + mt * 16 + r16) * 128 + kb)),
                       a[mt][0], a[mt][1], a[mt][2], a[mt][3]);
            #pragma unroll
            for (int q = 0; q < 4; ++q) {
                uint32_t r0, r1, r2, r3;
                ldm_x4(cur + B3_OFF +
                           SWZ128((uint32_t)((wn + q * 16 + r16) * 128 + kb)),
                       r0, r1, r2, r3);
                b[2 * q][0] = r0;     b[2 * q][1] = r2;
                b[2 * q + 1][0] = r1; b[2 * q + 1][1] = r3;
            }
            #pragma unroll
            for (int mt = 0; mt < 4; ++mt)
                #pragma unroll
                for (int nt = 0; nt < 8; ++nt)
                    mma_tf32(acc[mt][nt][0], acc[mt][nt][1],
                             acc[mt][nt][2], acc[mt][nt][3],
                             a[mt][0], a[mt][1], a[mt][2], a[mt][3],
                             b[nt][0], b[nt][1]);
        }
    }

    const int er = lane >> 2, ec = (lane & 3) * 2;
    #pragma unroll
    for (int mt = 0; mt < 4; ++mt) {
        #pragma unroll
        for (int nt = 0; nt < 8; ++nt) {
            const int n = bn + wn + nt * 8 + ec;
            const float bv0 = bias[n], bv1 = bias[n + 1];
            #pragma unroll
            for (int half = 0; half < 2; ++half) {
                const int m = bm + wm + mt * 16 + er + half * 8;
                float h0 = acc[mt][nt][half * 2 + 0] + bv0;
                float h1 = acc[mt][nt][half * 2 + 1] + bv1;
                float2 o2;
                o2.x = h0 > 0.f ? h0 : 0.01f * h0;
                o2.y = h1 > 0.f ? h1 : 0.01f * h1;
                *(float2*)&out[(size_t)m * 1024 + n] = o2;
            }
        }
    }
}

// ---------------------------------------------------------------------------
extern "C" void kernel_launch(void* const* d_in, const int* in_sizes, int n_in,
                              void* d_out, int out_size) {
    const float* base = (const float*)d_in[0];
    const int*   rois = (const int*)d_in[1];
    const float* w1   = (const float*)d_in[2];
    const float* b1   = (const float*)d_in[3];
    const float* w2   = (const float*)d_in[4];
    const float* b2   = (const float*)d_in[5];
    const float* wl   = (const float*)d_in[6];
    const float* bl   = (const float*)d_in[7];
    float* out = (float*)d_out;

    cudaFuncSetAttribute(zgemm_kernel, cudaFuncAttributeMaxDynamicSharedMemorySize,
                         ZG_SMEM);
    cudaFuncSetAttribute(gemm3_kernel, cudaFuncAttributeMaxDynamicSharedMemorySize,
                         GEMM_SMEM);

    prep_all<<<PREP_GRID, 256>>>(w1, b1, w2, wl, base);
    zgemm_kernel<<<NSAMP / 32, 256, ZG_SMEM>>>(rois, b2);
    gemm3_kernel<<<dim3(1024 / 128, NSAMP / 256), 256, GEMM_SMEM>>>(bl, out);
}